// round 1
// baseline (speedup 1.0000x reference)
#include <cuda_runtime.h>
#include <math.h>

#define BB 8
#define CC 256
#define HFD 160
#define WFD 160
#define NN 128
#define SS 7
#define HP 161                 // padded plane dim
#define PLANE (HP*HP)          // 25921
#define NBOX (BB*NN)           // 1024
#define NREG (SS*SS)           // 49
#define RF_ELEMS ((size_t)NBOX*CC*NREG)  // 12,845,056

// -------- scratch (static device allocs only) --------
__device__ float g_Ichw[(size_t)BB*CC*PLANE];   // integral, channel-major
__device__ float g_Ihwc[(size_t)BB*PLANE*CC];   // integral, channel-last
__device__ float g_reg [(size_t)NBOX*NREG*CC];  // region averages [box][region][c]

// ============================================================
// K1: 2D inclusive prefix-sum per (b,c) plane, padded output.
// One CTA per (b,c). Dynamic smem tile [160][161] (103 KB).
// ============================================================
__global__ void k_integral(const float* __restrict__ fm) {
    extern __shared__ float t[];            // [HFD][WFD+1] stride 161
    const int bc = blockIdx.x;
    const float* in = fm + (size_t)bc * (HFD*WFD);
    float* out = g_Ichw + (size_t)bc * PLANE;
    const int tid = threadIdx.x;

    // coalesced load into padded smem
    for (int idx = tid; idx < HFD*WFD; idx += blockDim.x) {
        int h = idx / WFD, w = idx - h*WFD;
        t[h*(WFD+1) + w] = in[idx];
    }
    __syncthreads();

    // row scan: thread = row, addresses stride 161 -> conflict-free
    if (tid < HFD) {
        float s = 0.f;
        float* row = t + tid*(WFD+1);
        #pragma unroll 4
        for (int w = 0; w < WFD; ++w) { s += row[w]; row[w] = s; }
    }
    __syncthreads();

    // column scan: thread = column, consecutive banks
    if (tid < WFD) {
        float s = 0.f;
        float* p = t + tid;
        #pragma unroll 4
        for (int h = 0; h < HFD; ++h) { s += p[h*(WFD+1)]; p[h*(WFD+1)] = s; }
    }
    __syncthreads();

    // padded write (first row/col zero)
    for (int idx = tid; idx < PLANE; idx += blockDim.x) {
        int r = idx / HP, c = idx - r*HP;
        out[idx] = (r == 0 || c == 0) ? 0.f : t[(r-1)*(WFD+1) + (c-1)];
    }
}

// ============================================================
// K2: transpose I[b][c][p] -> I[b][p][c] with 32x33 smem tiles.
// grid: (ceil(PLANE/32), CC/32, BB), block (32,32)
// ============================================================
__global__ void k_transpose() {
    __shared__ float tile[32][33];
    const int b  = blockIdx.z;
    const int cg = blockIdx.y;
    const int p0 = blockIdx.x * 32;
    const int tx = threadIdx.x, ty = threadIdx.y;

    {
        int c = cg*32 + ty;
        int p = p0 + tx;
        if (p < PLANE)
            tile[ty][tx] = g_Ichw[((size_t)(b*CC + c))*PLANE + p];
    }
    __syncthreads();
    {
        int c = cg*32 + tx;
        int p = p0 + ty;
        if (p < PLANE)
            g_Ihwc[((size_t)b*PLANE + p)*CC + c] = tile[tx][ty];
    }
}

// ============================================================
// K3: per-box corner gather + region average. CTA=box, thread=channel.
// Also writes area_ratios.
// ============================================================
__global__ void k_gather(const float* __restrict__ bboxes,
                         float* __restrict__ out_area) {
    const int box = blockIdx.x;          // 0..1023
    const int b   = box >> 7;            // /128
    const int c   = threadIdx.x;         // 0..255

    const float bx1 = bboxes[box*4+0];
    const float by1 = bboxes[box*4+1];
    const float bx2 = bboxes[box*4+2];
    const float by2 = bboxes[box*4+3];
    if (c == 0) out_area[box] = (bx2-bx1)*(by2-by1);

    // sx = sy = 160/640 = 0.25 exactly
    int x1 = (int)floorf(bx1*0.25f); x1 = min(max(x1, 0), WFD-1);
    int y1 = (int)floorf(by1*0.25f); y1 = min(max(y1, 0), HFD-1);
    int x2 = (int)floorf(bx2*0.25f); x2 = min(max(x2, x1+1), WFD);
    int y2 = (int)floorf(by2*0.25f); y2 = min(max(y2, y1+1), HFD);
    const int Lx = x2 - x1, Ly = y2 - y1;

    int rs[SS], re[SS], cs[SS], ce[SS];
    #pragma unroll
    for (int i = 0; i < SS; ++i) {
        rs[i] = y1 + (i*Ly)/SS;
        re[i] = y1 + ((i+1)*Ly + SS-1)/SS;
        cs[i] = x1 + (i*Lx)/SS;
        ce[i] = x1 + ((i+1)*Lx + SS-1)/SS;
    }

    const float* I = g_Ihwc + (size_t)b*PLANE*CC + c;
    float* outp = g_reg + (size_t)box*(NREG*CC) + c;

    #pragma unroll
    for (int i = 0; i < SS; ++i) {
        const float* rowS = I + (size_t)rs[i]*HP*CC;
        const float* rowE = I + (size_t)re[i]*HP*CC;
        const float dh = (float)(re[i]-rs[i]);
        #pragma unroll
        for (int j = 0; j < SS; ++j) {
            float tl = rowS[(size_t)cs[j]*CC];
            float tr = rowS[(size_t)ce[j]*CC];
            float bl = rowE[(size_t)cs[j]*CC];
            float br = rowE[(size_t)ce[j]*CC];
            float cnt = dh * (float)(ce[j]-cs[j]);
            outp[(i*SS+j)*CC] = (br - tr - bl + tl) / cnt;
        }
    }
}

// ============================================================
// K4: per-box GEMM  Out[256 o][49 r] = W[256x256] @ X[256 c][49 r] + bias
// block 224 threads = 32 o-groups(x8) * 7 r-groups(x7); dynamic smem.
// Xs: [49 r][c] stride 257 (50.4 KB); Wt: [o][32 cc] stride 33 (33.8 KB)
// ============================================================
#define XS_STRIDE 257
#define WT_STRIDE 33
#define K4_SMEM ((NREG*XS_STRIDE + 256*WT_STRIDE)*4)

__global__ void __launch_bounds__(224) k_gemm(const float* __restrict__ Wm,
                                              const float* __restrict__ bias,
                                              float* __restrict__ out) {
    extern __shared__ float sm[];
    float* Xs = sm;                       // [49][257]
    float* Wt = sm + NREG*XS_STRIDE;      // [256][33]

    const int box = blockIdx.x;
    const int tid = threadIdx.x;
    const int og  = tid / 7;              // 0..31 -> o = og*8+a
    const int rg  = tid % 7;              // 0..6  -> r = rg*7+k

    // load X[box]: stored as [j][c] contiguous
    const float* X = g_reg + (size_t)box*(NREG*CC);
    for (int idx = tid; idx < NREG*CC; idx += 224) {
        int j = idx >> 8, cc = idx & 255;
        Xs[j*XS_STRIDE + cc] = X[idx];
    }

    float acc[8][7];
    #pragma unroll
    for (int a = 0; a < 8; ++a)
        #pragma unroll
        for (int k = 0; k < 7; ++k) acc[a][k] = 0.f;

    for (int ct = 0; ct < 8; ++ct) {
        __syncthreads();   // Xs ready (iter 0) / Wt reuse safe (iters >0)
        for (int idx = tid; idx < 256*32; idx += 224) {
            int o = idx >> 5, cc = idx & 31;
            Wt[o*WT_STRIDE + cc] = Wm[o*256 + ct*32 + cc];
        }
        __syncthreads();

        #pragma unroll 8
        for (int cc = 0; cc < 32; ++cc) {
            const int cg = ct*32 + cc;
            float x[7], w[8];
            #pragma unroll
            for (int k = 0; k < 7; ++k) x[k] = Xs[(rg*7+k)*XS_STRIDE + cg];
            #pragma unroll
            for (int a = 0; a < 8; ++a) w[a] = Wt[(og*8+a)*WT_STRIDE + cc];
            #pragma unroll
            for (int a = 0; a < 8; ++a)
                #pragma unroll
                for (int k = 0; k < 7; ++k)
                    acc[a][k] = fmaf(w[a], x[k], acc[a][k]);
        }
    }

    float* ob = out + (size_t)box * CC * NREG;
    #pragma unroll
    for (int a = 0; a < 8; ++a) {
        const int o = og*8 + a;
        const float bv = bias[o];
        #pragma unroll
        for (int k = 0; k < 7; ++k)
            ob[o*NREG + rg*7 + k] = acc[a][k] + bv;
    }
}

// ============================================================
extern "C" void kernel_launch(void* const* d_in, const int* in_sizes, int n_in,
                              void* d_out, int out_size) {
    const float* fm     = (const float*)d_in[0];
    const float* bboxes = (const float*)d_in[1];
    const float* Wm     = (const float*)d_in[2];
    const float* bias   = (const float*)d_in[3];
    float* out = (float*)d_out;

    cudaFuncSetAttribute(k_integral, cudaFuncAttributeMaxDynamicSharedMemorySize,
                         HFD*(WFD+1)*4);
    cudaFuncSetAttribute(k_gemm, cudaFuncAttributeMaxDynamicSharedMemorySize,
                         K4_SMEM);

    k_integral<<<BB*CC, 256, HFD*(WFD+1)*4>>>(fm);

    dim3 g2((PLANE + 31)/32, CC/32, BB);
    k_transpose<<<g2, dim3(32,32)>>>();

    k_gather<<<NBOX, CC>>>(bboxes, out + RF_ELEMS);

    k_gemm<<<NBOX, 224, K4_SMEM>>>(Wm, bias, out);
}

// round 2
// speedup vs baseline: 1.2916x; 1.2916x over previous
#include <cuda_runtime.h>
#include <math.h>

#define BB 8
#define CC 256
#define HFD 160
#define WFD 160
#define NN 128
#define SS 7
#define HP 161
#define NBOX (BB*NN)                       // 1024
#define NREG (SS*SS)                       // 49
#define NTOT (NBOX*NREG)                   // 50176
#define RF_ELEMS ((size_t)NBOX*CC*NREG)    // 12,845,056

// -------- scratch --------
__device__ float g_rows[(size_t)BB*HFD*WFD*CC];   // row-scanned, layout [b][h][w][c]
__device__ float g_I   [(size_t)BB*HP*HP*CC];     // padded integral, [b][hp][wp][c]
__device__ float g_reg [(size_t)NTOT*CC];         // region averages [n=box*49+r][c]

// ============================================================
// K1: row prefix sums, fused transpose to channel-last.
// CTA = (b, h, 32-channel slab). smem [32][161].
// ============================================================
__global__ void __launch_bounds__(256) k_rowscan(const float* __restrict__ fm) {
    __shared__ float s[32*(WFD+1)];
    const int b  = blockIdx.z;
    const int h  = blockIdx.y;
    const int c0 = blockIdx.x * 32;
    const int tid = threadIdx.x;
    const int warp = tid >> 5, lane = tid & 31;

    // load 32 channel-rows, each 160 floats (coalesced)
    const float* in = fm + (((size_t)(b*CC + c0))*HFD + h)*WFD;
    for (int idx = tid; idx < 32*WFD; idx += 256) {
        int c = idx / WFD, w = idx - c*WFD;
        s[c*(WFD+1) + w] = in[(size_t)c*HFD*WFD + w];
    }
    __syncthreads();

    // warp-shuffle inclusive scan: each warp does 4 rows, 5 chunks of 32
    for (int r = warp; r < 32; r += 8) {
        float carry = 0.f;
        float* row = s + r*(WFD+1);
        #pragma unroll
        for (int ch = 0; ch < 5; ++ch) {
            float v = row[ch*32 + lane];
            #pragma unroll
            for (int off = 1; off < 32; off <<= 1) {
                float nv = __shfl_up_sync(0xffffffffu, v, off);
                if (lane >= off) v += nv;
            }
            v += carry;
            row[ch*32 + lane] = v;
            carry = __shfl_sync(0xffffffffu, v, 31);
        }
    }
    __syncthreads();

    // transposed write: [b][h][w][c0+c], 128B chunks coalesced
    float* out = g_rows + (((size_t)(b*HFD + h))*WFD)*CC + c0;
    for (int idx = tid; idx < 32*WFD; idx += 256) {
        int c = idx & 31, w = idx >> 5;
        out[(size_t)w*CC + c] = s[c*(WFD+1) + w];   // stride 161 -> conflict-free
    }
}

// ============================================================
// K2: column scan in channel-last layout, writes padded integral.
// CTA = (b, wp). thread = channel. Fully coalesced.
// ============================================================
__global__ void __launch_bounds__(256) k_colscan() {
    const int b  = blockIdx.y;
    const int wp = blockIdx.x;          // 0..160
    const int c  = threadIdx.x;

    float* out = g_I + (((size_t)b*HP)*HP + wp)*CC + c;
    const size_t orow = (size_t)HP*CC;

    out[0] = 0.f;                        // hp = 0
    if (wp == 0) {
        for (int hp = 1; hp <= HFD; ++hp) out[(size_t)hp*orow] = 0.f;
        return;
    }
    const int w = wp - 1;
    const float* in = g_rows + (((size_t)b*HFD)*WFD + w)*CC + c;
    const size_t irow = (size_t)WFD*CC;
    float acc = 0.f;
    #pragma unroll 4
    for (int h = 0; h < HFD; ++h) {
        acc += in[(size_t)h*irow];
        out[(size_t)(h+1)*orow] = acc;
    }
}

// ============================================================
// K3: per-box corner gather + region average + area ratios.
// ============================================================
__global__ void k_gather(const float* __restrict__ bboxes,
                         float* __restrict__ out_area) {
    const int box = blockIdx.x;
    const int b   = box >> 7;
    const int c   = threadIdx.x;

    const float bx1 = bboxes[box*4+0];
    const float by1 = bboxes[box*4+1];
    const float bx2 = bboxes[box*4+2];
    const float by2 = bboxes[box*4+3];
    if (c == 0) out_area[box] = (bx2-bx1)*(by2-by1);

    int x1 = (int)floorf(bx1*0.25f); x1 = min(max(x1, 0), WFD-1);
    int y1 = (int)floorf(by1*0.25f); y1 = min(max(y1, 0), HFD-1);
    int x2 = (int)floorf(bx2*0.25f); x2 = min(max(x2, x1+1), WFD);
    int y2 = (int)floorf(by2*0.25f); y2 = min(max(y2, y1+1), HFD);
    const int Lx = x2 - x1, Ly = y2 - y1;

    int rs[SS], re[SS], cs[SS], ce[SS];
    #pragma unroll
    for (int i = 0; i < SS; ++i) {
        rs[i] = y1 + (i*Ly)/SS;
        re[i] = y1 + ((i+1)*Ly + SS-1)/SS;
        cs[i] = x1 + (i*Lx)/SS;
        ce[i] = x1 + ((i+1)*Lx + SS-1)/SS;
    }

    const float* I = g_I + (size_t)b*HP*HP*CC + c;
    float* outp = g_reg + (size_t)box*(NREG*CC) + c;

    #pragma unroll
    for (int i = 0; i < SS; ++i) {
        const float* rowS = I + (size_t)rs[i]*HP*CC;
        const float* rowE = I + (size_t)re[i]*HP*CC;
        const float dh = (float)(re[i]-rs[i]);
        #pragma unroll
        for (int j = 0; j < SS; ++j) {
            float tl = rowS[(size_t)cs[j]*CC];
            float tr = rowS[(size_t)ce[j]*CC];
            float bl = rowE[(size_t)cs[j]*CC];
            float br = rowE[(size_t)ce[j]*CC];
            float cnt = dh * (float)(ce[j]-cs[j]);
            outp[(i*SS+j)*CC] = (br - tr - bl + tl) / cnt;
        }
    }
}

// ============================================================
// K4: one global GEMM Out[m=256][n=50176] = W[256x256] @ X^T + bias
// X = g_reg [n][k=256]. Tiles 128x128x16, double-buffered, 8x8/thread.
// ============================================================
#define TK 16
#define LDT 132    // 128 + 4 pad

__global__ void __launch_bounds__(256) k_gemm2(const float* __restrict__ Wm,
                                               const float* __restrict__ bias,
                                               float* __restrict__ out) {
    __shared__ float As[2][TK][LDT];
    __shared__ float Bs[2][TK][LDT];

    const int tid = threadIdx.x;
    const int n0 = blockIdx.x * 128;
    const int m0 = blockIdx.y * 128;

    const int lr = tid >> 1;              // 0..127
    const int lk = (tid & 1) * 8;         // 0 / 8

    const float* aptr = Wm + (size_t)(m0 + lr)*CC + lk;
    const float* bptr = g_reg + (size_t)(n0 + lr)*CC + lk;

    const int ty = tid >> 4;              // m octet
    const int tx = tid & 15;              // n octet

    float acc[8][8];
    #pragma unroll
    for (int a = 0; a < 8; ++a)
        #pragma unroll
        for (int k = 0; k < 8; ++k) acc[a][k] = 0.f;

    // prologue: fill buffer 0 (kt = 0)
    {
        float4 a0 = *(const float4*)(aptr);
        float4 a1 = *(const float4*)(aptr + 4);
        float4 b0 = *(const float4*)(bptr);
        float4 b1 = *(const float4*)(bptr + 4);
        As[0][lk+0][lr]=a0.x; As[0][lk+1][lr]=a0.y; As[0][lk+2][lr]=a0.z; As[0][lk+3][lr]=a0.w;
        As[0][lk+4][lr]=a1.x; As[0][lk+5][lr]=a1.y; As[0][lk+6][lr]=a1.z; As[0][lk+7][lr]=a1.w;
        Bs[0][lk+0][lr]=b0.x; Bs[0][lk+1][lr]=b0.y; Bs[0][lk+2][lr]=b0.z; Bs[0][lk+3][lr]=b0.w;
        Bs[0][lk+4][lr]=b1.x; Bs[0][lk+5][lr]=b1.y; Bs[0][lk+6][lr]=b1.z; Bs[0][lk+7][lr]=b1.w;
    }
    __syncthreads();

    #pragma unroll 1
    for (int kt = 0; kt < CC/TK; ++kt) {
        const int cur = kt & 1;
        float4 a0, a1, b0, b1;
        if (kt < CC/TK - 1) {
            const float* ap = aptr + (kt+1)*TK;
            const float* bp = bptr + (kt+1)*TK;
            a0 = *(const float4*)(ap);
            a1 = *(const float4*)(ap + 4);
            b0 = *(const float4*)(bp);
            b1 = *(const float4*)(bp + 4);
        }

        #pragma unroll
        for (int kk = 0; kk < TK; ++kk) {
            float4 wa0 = *(const float4*)&As[cur][kk][ty*8];
            float4 wa1 = *(const float4*)&As[cur][kk][ty*8+4];
            float4 xb0 = *(const float4*)&Bs[cur][kk][tx*8];
            float4 xb1 = *(const float4*)&Bs[cur][kk][tx*8+4];
            float wv[8] = {wa0.x,wa0.y,wa0.z,wa0.w,wa1.x,wa1.y,wa1.z,wa1.w};
            float xv[8] = {xb0.x,xb0.y,xb0.z,xb0.w,xb1.x,xb1.y,xb1.z,xb1.w};
            #pragma unroll
            for (int a = 0; a < 8; ++a)
                #pragma unroll
                for (int k = 0; k < 8; ++k)
                    acc[a][k] = fmaf(wv[a], xv[k], acc[a][k]);
        }

        if (kt < CC/TK - 1) {
            const int nxt = 1 - cur;
            As[nxt][lk+0][lr]=a0.x; As[nxt][lk+1][lr]=a0.y; As[nxt][lk+2][lr]=a0.z; As[nxt][lk+3][lr]=a0.w;
            As[nxt][lk+4][lr]=a1.x; As[nxt][lk+5][lr]=a1.y; As[nxt][lk+6][lr]=a1.z; As[nxt][lk+7][lr]=a1.w;
            Bs[nxt][lk+0][lr]=b0.x; Bs[nxt][lk+1][lr]=b0.y; Bs[nxt][lk+2][lr]=b0.z; Bs[nxt][lk+3][lr]=b0.w;
            Bs[nxt][lk+4][lr]=b1.x; Bs[nxt][lk+5][lr]=b1.y; Bs[nxt][lk+6][lr]=b1.z; Bs[nxt][lk+7][lr]=b1.w;
        }
        __syncthreads();
    }

    // epilogue: out[box][o][r], n = box*49 + r
    #pragma unroll
    for (int a = 0; a < 8; ++a) {
        const int o = m0 + ty*8 + a;
        const float bv = bias[o];
        int n = n0 + tx*8;
        int box = n / NREG;
        int r = n - box*NREG;
        #pragma unroll
        for (int k = 0; k < 8; ++k) {
            out[(size_t)box*(CC*NREG) + (size_t)o*NREG + r] = acc[a][k] + bv;
            if (++r == NREG) { r = 0; ++box; }
        }
    }
}

// ============================================================
extern "C" void kernel_launch(void* const* d_in, const int* in_sizes, int n_in,
                              void* d_out, int out_size) {
    const float* fm     = (const float*)d_in[0];
    const float* bboxes = (const float*)d_in[1];
    const float* Wm     = (const float*)d_in[2];
    const float* bias   = (const float*)d_in[3];
    float* out = (float*)d_out;

    dim3 g1(CC/32, HFD, BB);                 // 8 x 160 x 8
    k_rowscan<<<g1, 256>>>(fm);

    dim3 g2(HP, BB);                          // 161 x 8
    k_colscan<<<g2, 256>>>();

    k_gather<<<NBOX, CC>>>(bboxes, out + RF_ELEMS);

    dim3 g4(NTOT/128, 2);                     // 392 x 2
    k_gemm2<<<g4, 256>>>(Wm, bias, out);
}

// round 4
// speedup vs baseline: 1.7468x; 1.3524x over previous
#include <cuda_runtime.h>
#include <cuda_fp16.h>
#include <math.h>
#include <stdint.h>

#define BB 8
#define CC 256
#define HFD 160
#define WFD 160
#define NN 128
#define SS 7
#define HP 161
#define NBOX (BB*NN)                       // 1024
#define NREG (SS*SS)                       // 49
#define NTOT (NBOX*NREG)                   // 50176
#define RF_ELEMS ((size_t)NBOX*CC*NREG)    // 12,845,056

// -------- scratch --------
__device__ float  g_rows[(size_t)BB*HFD*WFD*CC];   // row-scanned, [b][h][w][c]
__device__ float  g_I   [(size_t)BB*HP*HP*CC];     // padded integral, [b][hp][wp][c]
__device__ __align__(16) __half g_regh[(size_t)NTOT*CC];  // region avgs fp16 [n][c]
__device__ __align__(16) __half g_Wh[CC*CC];              // W fp16 [o][c]

__device__ __forceinline__ uint32_t smem_u32(const void* p) {
    uint32_t a;
    asm("{ .reg .u64 t; cvta.to.shared.u64 t, %1; cvt.u32.u64 %0, t; }"
        : "=r"(a) : "l"(p));
    return a;
}

// ============================================================
// K0: W -> fp16
// ============================================================
__global__ void k_convw(const float* __restrict__ Wm) {
    int i = blockIdx.x * 256 + threadIdx.x;
    g_Wh[i] = __float2half_rn(Wm[i]);
}

// ============================================================
// K1: row prefix sums, fused transpose to channel-last.
// ============================================================
__global__ void __launch_bounds__(256) k_rowscan(const float* __restrict__ fm) {
    __shared__ float s[32*(WFD+1)];
    const int b  = blockIdx.z;
    const int h  = blockIdx.y;
    const int c0 = blockIdx.x * 32;
    const int tid = threadIdx.x;
    const int warp = tid >> 5, lane = tid & 31;

    const float* in = fm + (((size_t)(b*CC + c0))*HFD + h)*WFD;
    for (int idx = tid; idx < 32*WFD; idx += 256) {
        int c = idx / WFD, w = idx - c*WFD;
        s[c*(WFD+1) + w] = in[(size_t)c*HFD*WFD + w];
    }
    __syncthreads();

    for (int r = warp; r < 32; r += 8) {
        float carry = 0.f;
        float* row = s + r*(WFD+1);
        #pragma unroll
        for (int ch = 0; ch < 5; ++ch) {
            float v = row[ch*32 + lane];
            #pragma unroll
            for (int off = 1; off < 32; off <<= 1) {
                float nv = __shfl_up_sync(0xffffffffu, v, off);
                if (lane >= off) v += nv;
            }
            v += carry;
            row[ch*32 + lane] = v;
            carry = __shfl_sync(0xffffffffu, v, 31);
        }
    }
    __syncthreads();

    float* out = g_rows + (((size_t)(b*HFD + h))*WFD)*CC + c0;
    for (int idx = tid; idx < 32*WFD; idx += 256) {
        int c = idx & 31, w = idx >> 5;
        out[(size_t)w*CC + c] = s[c*(WFD+1) + w];
    }
}

// ============================================================
// K2: column scan, channel-last, writes padded integral.
// ============================================================
__global__ void __launch_bounds__(256) k_colscan() {
    const int b  = blockIdx.y;
    const int wp = blockIdx.x;
    const int c  = threadIdx.x;

    float* out = g_I + (((size_t)b*HP)*HP + wp)*CC + c;
    const size_t orow = (size_t)HP*CC;

    out[0] = 0.f;
    if (wp == 0) {
        for (int hp = 1; hp <= HFD; ++hp) out[(size_t)hp*orow] = 0.f;
        return;
    }
    const int w = wp - 1;
    const float* in = g_rows + (((size_t)b*HFD)*WFD + w)*CC + c;
    const size_t irow = (size_t)WFD*CC;
    float acc = 0.f;
    #pragma unroll 8
    for (int h = 0; h < HFD; ++h) {
        acc += in[(size_t)h*irow];
        out[(size_t)(h+1)*orow] = acc;
    }
}

// ============================================================
// K3: per-box corner gather + region average (fp16 out) + areas.
// ============================================================
__global__ void k_gather(const float* __restrict__ bboxes,
                         float* __restrict__ out_area) {
    const int box = blockIdx.x;
    const int b   = box >> 7;
    const int c   = threadIdx.x;

    const float bx1 = bboxes[box*4+0];
    const float by1 = bboxes[box*4+1];
    const float bx2 = bboxes[box*4+2];
    const float by2 = bboxes[box*4+3];
    if (c == 0) out_area[box] = (bx2-bx1)*(by2-by1);

    int x1 = (int)floorf(bx1*0.25f); x1 = min(max(x1, 0), WFD-1);
    int y1 = (int)floorf(by1*0.25f); y1 = min(max(y1, 0), HFD-1);
    int x2 = (int)floorf(bx2*0.25f); x2 = min(max(x2, x1+1), WFD);
    int y2 = (int)floorf(by2*0.25f); y2 = min(max(y2, y1+1), HFD);
    const int Lx = x2 - x1, Ly = y2 - y1;

    int rs[SS], re[SS], cs[SS], ce[SS];
    #pragma unroll
    for (int i = 0; i < SS; ++i) {
        rs[i] = y1 + (i*Ly)/SS;
        re[i] = y1 + ((i+1)*Ly + SS-1)/SS;
        cs[i] = x1 + (i*Lx)/SS;
        ce[i] = x1 + ((i+1)*Lx + SS-1)/SS;
    }

    const float* I = g_I + (size_t)b*HP*HP*CC + c;
    __half* outp = g_regh + (size_t)box*(NREG*CC) + c;

    #pragma unroll
    for (int i = 0; i < SS; ++i) {
        const float* rowS = I + (size_t)rs[i]*HP*CC;
        const float* rowE = I + (size_t)re[i]*HP*CC;
        const float dh = (float)(re[i]-rs[i]);
        #pragma unroll
        for (int j = 0; j < SS; ++j) {
            float tl = rowS[(size_t)cs[j]*CC];
            float tr = rowS[(size_t)ce[j]*CC];
            float bl = rowE[(size_t)cs[j]*CC];
            float br = rowE[(size_t)ce[j]*CC];
            float cnt = dh * (float)(ce[j]-cs[j]);
            outp[(i*SS+j)*CC] = __float2half_rn((br - tr - bl + tl) / cnt);
        }
    }
}

// ============================================================
// K4: mma.sync (m16n8k16 f16) GEMM.
// D[128m x 128n] = Wh[m][k=256] @ Xh[n][k]^T + bias
// CTA: 256 thr = 8 warps, warp tile 64m x 32n, full K resident in smem.
// A/B smem: [row][256 halves], 16B chunks swizzled kb ^= row&7.
// grid = (2 m-tiles, 392 n-tiles).
// ============================================================
#define GSM_B_OFF 65536
#define GEMM_SMEM 131072
#define STG_LD 129

__global__ void __launch_bounds__(256) k_mma_gemm(const float* __restrict__ bias,
                                                  float* __restrict__ out) {
    extern __shared__ char sm[];
    const uint32_t sb = smem_u32(sm);
    const int tid = threadIdx.x, wid = tid >> 5, lane = tid & 31;
    const int m0 = blockIdx.x * 128;
    const int n0 = blockIdx.y * 128;

    // ---- load A (W) and B (X) tiles into swizzled smem ----
    #pragma unroll
    for (int it = 0; it < 16; ++it) {
        int i = tid + it*256;             // 0..4095
        int row = i >> 5, kb = i & 31;
        uint32_t off = (uint32_t)(row*512 + ((kb ^ (row & 7)) << 4));
        *(uint4*)(sm + off) =
            *(const uint4*)(g_Wh + (size_t)(m0 + row)*CC + kb*8);
        *(uint4*)(sm + GSM_B_OFF + off) =
            *(const uint4*)(g_regh + (size_t)(n0 + row)*CC + kb*8);
    }
    __syncthreads();

    const int wm = wid >> 2;              // 0..1 -> m quad
    const int wn = wid & 3;               // 0..3 -> n quad

    // per-lane ldmatrix addressing
    // A: x4, lane l -> row = mbase + (l&15), k-half = l>>4
    const int a_l15 = lane & 15;
    const int a_khi = lane >> 4;          // 0/1
    // B: x2, lanes 0-15 used; row = nbase + (l&7), k-half = (l>>3)&1
    const int b_l7  = lane & 7;
    const int b_khi = (lane >> 3) & 1;

    uint32_t a_base[4], a_xr[4];
    #pragma unroll
    for (int mf = 0; mf < 4; ++mf) {
        int mrow = wm*64 + mf*16 + a_l15;
        a_base[mf] = sb + mrow*512;
        a_xr[mf] = (uint32_t)(mrow & 7);
    }
    uint32_t b_base[4], b_xr[4];
    #pragma unroll
    for (int nf = 0; nf < 4; ++nf) {
        int nrow = wn*32 + nf*8 + b_l7;
        b_base[nf] = sb + GSM_B_OFF + nrow*512;
        b_xr[nf] = (uint32_t)(nrow & 7);
    }

    float acc[4][4][4];
    #pragma unroll
    for (int mf = 0; mf < 4; ++mf)
        #pragma unroll
        for (int nf = 0; nf < 4; ++nf)
            #pragma unroll
            for (int e = 0; e < 4; ++e) acc[mf][nf][e] = 0.f;

    #pragma unroll
    for (int ks = 0; ks < 16; ++ks) {
        uint32_t a[4][4], b[4][2];
        #pragma unroll
        for (int mf = 0; mf < 4; ++mf) {
            uint32_t kb = (uint32_t)(ks*2 + a_khi) ^ a_xr[mf];
            uint32_t addr = a_base[mf] + (kb << 4);
            asm volatile("ldmatrix.sync.aligned.m8n8.x4.shared.b16 {%0,%1,%2,%3}, [%4];"
                         : "=r"(a[mf][0]), "=r"(a[mf][1]), "=r"(a[mf][2]), "=r"(a[mf][3])
                         : "r"(addr));
        }
        #pragma unroll
        for (int nf = 0; nf < 4; ++nf) {
            uint32_t kb = (uint32_t)(ks*2 + b_khi) ^ b_xr[nf];
            uint32_t addr = b_base[nf] + (kb << 4);
            asm volatile("ldmatrix.sync.aligned.m8n8.x2.shared.b16 {%0,%1}, [%2];"
                         : "=r"(b[nf][0]), "=r"(b[nf][1])
                         : "r"(addr));
        }
        #pragma unroll
        for (int mf = 0; mf < 4; ++mf)
            #pragma unroll
            for (int nf = 0; nf < 4; ++nf) {
                asm volatile(
                    "mma.sync.aligned.m16n8k16.row.col.f32.f16.f16.f32 "
                    "{%0,%1,%2,%3}, {%4,%5,%6,%7}, {%8,%9}, {%0,%1,%2,%3};"
                    : "+f"(acc[mf][nf][0]), "+f"(acc[mf][nf][1]),
                      "+f"(acc[mf][nf][2]), "+f"(acc[mf][nf][3])
                    : "r"(a[mf][0]), "r"(a[mf][1]), "r"(a[mf][2]), "r"(a[mf][3]),
                      "r"(b[nf][0]), "r"(b[nf][1]));
            }
    }
    __syncthreads();   // done reading A/B smem; safe to overwrite with staging

    // ---- stage f32 result into smem [128][129] ----
    float* stg = (float*)sm;
    const int crow = lane >> 2;           // 0..7
    const int ccol = (lane & 3) * 2;      // 0,2,4,6
    #pragma unroll
    for (int mf = 0; mf < 4; ++mf) {
        int mr = wm*64 + mf*16 + crow;
        #pragma unroll
        for (int nf = 0; nf < 4; ++nf) {
            int nc = wn*32 + nf*8 + ccol;
            stg[mr*STG_LD + nc]         = acc[mf][nf][0];
            stg[mr*STG_LD + nc + 1]     = acc[mf][nf][1];
            stg[(mr+8)*STG_LD + nc]     = acc[mf][nf][2];
            stg[(mr+8)*STG_LD + nc + 1] = acc[mf][nf][3];
        }
    }
    __syncthreads();

    // ---- coalesced scatter to out[box][o][r]  (n = box*49 + r) ----
    #pragma unroll 4
    for (int i = tid; i < 128*128; i += 256) {
        int m = i >> 7, n = i & 127;
        int nn = n0 + n, o = m0 + m;
        int box = nn / NREG, r = nn - box*NREG;
        out[(size_t)box*(CC*NREG) + (size_t)o*NREG + r] = stg[m*STG_LD + n] + bias[o];
    }
}

// ============================================================
extern "C" void kernel_launch(void* const* d_in, const int* in_sizes, int n_in,
                              void* d_out, int out_size) {
    const float* fm     = (const float*)d_in[0];
    const float* bboxes = (const float*)d_in[1];
    const float* Wm     = (const float*)d_in[2];
    const float* bias   = (const float*)d_in[3];
    float* out = (float*)d_out;

    cudaFuncSetAttribute(k_mma_gemm, cudaFuncAttributeMaxDynamicSharedMemorySize,
                         GEMM_SMEM);

    k_convw<<<CC, 256>>>(Wm);

    dim3 g1(CC/32, HFD, BB);
    k_rowscan<<<g1, 256>>>(fm);

    dim3 g2(HP, BB);
    k_colscan<<<g2, 256>>>();

    k_gather<<<NBOX, CC>>>(bboxes, out + RF_ELEMS);

    dim3 g4(2, NTOT/128);
    k_mma_gemm<<<g4, 256, GEMM_SMEM>>>(bias, out);
}

// round 5
// speedup vs baseline: 2.9518x; 1.6898x over previous
#include <cuda_runtime.h>
#include <cuda_fp16.h>
#include <math.h>
#include <stdint.h>

#define BB 8
#define CC 256
#define HFD 160
#define WFD 160
#define NN 128
#define SS 7
#define HP 161
#define NBOX (BB*NN)                       // 1024
#define NREG (SS*SS)                       // 49
#define NTOT (NBOX*NREG)                   // 50176
#define RF_ELEMS ((size_t)NBOX*CC*NREG)    // 12,845,056
#define SLAB 8
#define CSTR 164                           // staging stride (bank-conflict-free)

// -------- scratch --------
__device__ float  g_I[(size_t)BB*HP*HP*CC];               // padded integral [b][hp][wp][c]
__device__ __align__(16) __half g_regh[(size_t)NTOT*CC];  // region avgs fp16 [n][c]
__device__ __align__(16) __half g_Wh[CC*CC];              // W fp16 [o][c]

__device__ __forceinline__ uint32_t smem_u32(const void* p) {
    uint32_t a;
    asm("{ .reg .u64 t; cvta.to.shared.u64 t, %1; cvt.u32.u64 %0, t; }"
        : "=r"(a) : "l"(p));
    return a;
}

// ============================================================
// K0: W -> fp16
// ============================================================
__global__ void k_convw(const float* __restrict__ Wm) {
    int i = blockIdx.x * 256 + threadIdx.x;
    g_Wh[i] = __float2half_rn(Wm[i]);
}

// ============================================================
// K1: fused single-pass 2D integral, channel-last padded output.
// CTA = (8-channel slab, batch); warp = one channel; colsum in regs.
// Per row: parallel-chunk shuffle scan + reg accumulation, then a
// double-buffered smem transpose stage -> coalesced float2 stores.
// ============================================================
__global__ void __launch_bounds__(256) k_integral(const float* __restrict__ fm) {
    __shared__ float stg[2][SLAB*CSTR];
    const int b  = blockIdx.y;
    const int c0 = blockIdx.x * SLAB;
    const int tid = threadIdx.x, w = tid >> 5, lane = tid & 31;
    const int c = c0 + w;

    const float* in  = fm + ((size_t)(b*CC + c)*HFD)*WFD;
    float* outb = g_I + (((size_t)b*HP)*HP)*CC + c0;

    // hp = 0 row: zeros (161 wp x 8 cc)
    for (int idx = tid; idx < HP*SLAB; idx += 256) {
        int wp = idx >> 3, cc = idx & 7;
        outb[(size_t)wp*CC + cc] = 0.f;
    }

    float colsum[5] = {0.f, 0.f, 0.f, 0.f, 0.f};
    float v[5];
    #pragma unroll
    for (int j = 0; j < 5; ++j) v[j] = in[j*32 + lane];

    for (int h = 0; h < HFD; ++h) {
        // prefetch next row while we scan this one
        float nv[5] = {0.f, 0.f, 0.f, 0.f, 0.f};
        if (h + 1 < HFD) {
            #pragma unroll
            for (int j = 0; j < 5; ++j) nv[j] = in[(size_t)(h+1)*WFD + j*32 + lane];
        }

        // parallel chunk scans (ILP-5 across chunks)
        #pragma unroll
        for (int off = 1; off < 32; off <<= 1) {
            #pragma unroll
            for (int j = 0; j < 5; ++j) {
                float n = __shfl_up_sync(0xffffffffu, v[j], off);
                if (lane >= off) v[j] += n;
            }
        }
        // chunk-total exclusive prefix
        float pre = 0.f;
        #pragma unroll
        for (int j = 0; j < 5; ++j) {
            float tot = __shfl_sync(0xffffffffu, v[j], 31);
            v[j] += pre;
            pre += tot;
        }

        const int p = h & 1;
        #pragma unroll
        for (int j = 0; j < 5; ++j) {
            colsum[j] += v[j];
            stg[p][w*CSTR + j*32 + lane] = colsum[j];
        }
        __syncthreads();

        // cooperative coalesced store of integral row hp = h+1 (wp=0 pad zero)
        float* orow = outb + (size_t)(h+1)*HP*CC;
        for (int idx = tid; idx < HP*4; idx += 256) {    // 644 float2 stores
            int wp = idx >> 2, cp = idx & 3;
            float2 val;
            if (wp == 0) { val.x = 0.f; val.y = 0.f; }
            else {
                val.x = stg[p][(cp*2    )*CSTR + (wp-1)];
                val.y = stg[p][(cp*2 + 1)*CSTR + (wp-1)];
            }
            *(float2*)(orow + (size_t)wp*CC + cp*2) = val;
        }

        #pragma unroll
        for (int j = 0; j < 5; ++j) v[j] = nv[j];
    }
}

// ============================================================
// K3: per-box corner gather + region average (fp16 out) + areas.
// ============================================================
__global__ void k_gather(const float* __restrict__ bboxes,
                         float* __restrict__ out_area) {
    const int box = blockIdx.x;
    const int b   = box >> 7;
    const int c   = threadIdx.x;

    const float bx1 = bboxes[box*4+0];
    const float by1 = bboxes[box*4+1];
    const float bx2 = bboxes[box*4+2];
    const float by2 = bboxes[box*4+3];
    if (c == 0) out_area[box] = (bx2-bx1)*(by2-by1);

    int x1 = (int)floorf(bx1*0.25f); x1 = min(max(x1, 0), WFD-1);
    int y1 = (int)floorf(by1*0.25f); y1 = min(max(y1, 0), HFD-1);
    int x2 = (int)floorf(bx2*0.25f); x2 = min(max(x2, x1+1), WFD);
    int y2 = (int)floorf(by2*0.25f); y2 = min(max(y2, y1+1), HFD);
    const int Lx = x2 - x1, Ly = y2 - y1;

    int rs[SS], re[SS], cs[SS], ce[SS];
    #pragma unroll
    for (int i = 0; i < SS; ++i) {
        rs[i] = y1 + (i*Ly)/SS;
        re[i] = y1 + ((i+1)*Ly + SS-1)/SS;
        cs[i] = x1 + (i*Lx)/SS;
        ce[i] = x1 + ((i+1)*Lx + SS-1)/SS;
    }

    const float* I = g_I + (size_t)b*HP*HP*CC + c;
    __half* outp = g_regh + (size_t)box*(NREG*CC) + c;

    #pragma unroll
    for (int i = 0; i < SS; ++i) {
        const float* rowS = I + (size_t)rs[i]*HP*CC;
        const float* rowE = I + (size_t)re[i]*HP*CC;
        const float dh = (float)(re[i]-rs[i]);
        #pragma unroll
        for (int j = 0; j < SS; ++j) {
            float tl = rowS[(size_t)cs[j]*CC];
            float tr = rowS[(size_t)ce[j]*CC];
            float bl = rowE[(size_t)cs[j]*CC];
            float br = rowE[(size_t)ce[j]*CC];
            float cnt = dh * (float)(ce[j]-cs[j]);
            outp[(i*SS+j)*CC] = __float2half_rn((br - tr - bl + tl) / cnt);
        }
    }
}

// ============================================================
// K4: mma.sync (m16n8k16 f16) GEMM.
// D[128m x 128n] = Wh[m][k=256] @ Xh[n][k]^T + bias
// ============================================================
#define GSM_B_OFF 65536
#define GEMM_SMEM 131072
#define STG_LD 129

__global__ void __launch_bounds__(256) k_mma_gemm(const float* __restrict__ bias,
                                                  float* __restrict__ out) {
    extern __shared__ char sm[];
    const uint32_t sb = smem_u32(sm);
    const int tid = threadIdx.x, wid = tid >> 5, lane = tid & 31;
    const int m0 = blockIdx.x * 128;
    const int n0 = blockIdx.y * 128;

    #pragma unroll
    for (int it = 0; it < 16; ++it) {
        int i = tid + it*256;
        int row = i >> 5, kb = i & 31;
        uint32_t off = (uint32_t)(row*512 + ((kb ^ (row & 7)) << 4));
        *(uint4*)(sm + off) =
            *(const uint4*)(g_Wh + (size_t)(m0 + row)*CC + kb*8);
        *(uint4*)(sm + GSM_B_OFF + off) =
            *(const uint4*)(g_regh + (size_t)(n0 + row)*CC + kb*8);
    }
    __syncthreads();

    const int wm = wid >> 2;
    const int wn = wid & 3;

    const int a_l15 = lane & 15;
    const int a_khi = lane >> 4;
    const int b_l7  = lane & 7;
    const int b_khi = (lane >> 3) & 1;

    uint32_t a_base[4], a_xr[4];
    #pragma unroll
    for (int mf = 0; mf < 4; ++mf) {
        int mrow = wm*64 + mf*16 + a_l15;
        a_base[mf] = sb + mrow*512;
        a_xr[mf] = (uint32_t)(mrow & 7);
    }
    uint32_t b_base[4], b_xr[4];
    #pragma unroll
    for (int nf = 0; nf < 4; ++nf) {
        int nrow = wn*32 + nf*8 + b_l7;
        b_base[nf] = sb + GSM_B_OFF + nrow*512;
        b_xr[nf] = (uint32_t)(nrow & 7);
    }

    float acc[4][4][4];
    #pragma unroll
    for (int mf = 0; mf < 4; ++mf)
        #pragma unroll
        for (int nf = 0; nf < 4; ++nf)
            #pragma unroll
            for (int e = 0; e < 4; ++e) acc[mf][nf][e] = 0.f;

    #pragma unroll
    for (int ks = 0; ks < 16; ++ks) {
        uint32_t a[4][4], b[4][2];
        #pragma unroll
        for (int mf = 0; mf < 4; ++mf) {
            uint32_t kb = (uint32_t)(ks*2 + a_khi) ^ a_xr[mf];
            uint32_t addr = a_base[mf] + (kb << 4);
            asm volatile("ldmatrix.sync.aligned.m8n8.x4.shared.b16 {%0,%1,%2,%3}, [%4];"
                         : "=r"(a[mf][0]), "=r"(a[mf][1]), "=r"(a[mf][2]), "=r"(a[mf][3])
                         : "r"(addr));
        }
        #pragma unroll
        for (int nf = 0; nf < 4; ++nf) {
            uint32_t kb = (uint32_t)(ks*2 + b_khi) ^ b_xr[nf];
            uint32_t addr = b_base[nf] + (kb << 4);
            asm volatile("ldmatrix.sync.aligned.m8n8.x2.shared.b16 {%0,%1}, [%2];"
                         : "=r"(b[nf][0]), "=r"(b[nf][1])
                         : "r"(addr));
        }
        #pragma unroll
        for (int mf = 0; mf < 4; ++mf)
            #pragma unroll
            for (int nf = 0; nf < 4; ++nf) {
                asm volatile(
                    "mma.sync.aligned.m16n8k16.row.col.f32.f16.f16.f32 "
                    "{%0,%1,%2,%3}, {%4,%5,%6,%7}, {%8,%9}, {%0,%1,%2,%3};"
                    : "+f"(acc[mf][nf][0]), "+f"(acc[mf][nf][1]),
                      "+f"(acc[mf][nf][2]), "+f"(acc[mf][nf][3])
                    : "r"(a[mf][0]), "r"(a[mf][1]), "r"(a[mf][2]), "r"(a[mf][3]),
                      "r"(b[nf][0]), "r"(b[nf][1]));
            }
    }
    __syncthreads();

    float* stgf = (float*)sm;
    const int crow = lane >> 2;
    const int ccol = (lane & 3) * 2;
    #pragma unroll
    for (int mf = 0; mf < 4; ++mf) {
        int mr = wm*64 + mf*16 + crow;
        #pragma unroll
        for (int nf = 0; nf < 4; ++nf) {
            int nc = wn*32 + nf*8 + ccol;
            stgf[mr*STG_LD + nc]         = acc[mf][nf][0];
            stgf[mr*STG_LD + nc + 1]     = acc[mf][nf][1];
            stgf[(mr+8)*STG_LD + nc]     = acc[mf][nf][2];
            stgf[(mr+8)*STG_LD + nc + 1] = acc[mf][nf][3];
        }
    }
    __syncthreads();

    #pragma unroll 4
    for (int i = tid; i < 128*128; i += 256) {
        int m = i >> 7, n = i & 127;
        int nn = n0 + n, o = m0 + m;
        int box = nn / NREG, r = nn - box*NREG;
        out[(size_t)box*(CC*NREG) + (size_t)o*NREG + r] = stgf[m*STG_LD + n] + bias[o];
    }
}

// ============================================================
extern "C" void kernel_launch(void* const* d_in, const int* in_sizes, int n_in,
                              void* d_out, int out_size) {
    const float* fm     = (const float*)d_in[0];
    const float* bboxes = (const float*)d_in[1];
    const float* Wm     = (const float*)d_in[2];
    const float* bias   = (const float*)d_in[3];
    float* out = (float*)d_out;

    cudaFuncSetAttribute(k_mma_gemm, cudaFuncAttributeMaxDynamicSharedMemorySize,
                         GEMM_SMEM);

    k_convw<<<CC, 256>>>(Wm);

    dim3 g1(CC/SLAB, BB);                 // 32 x 8 = 256 CTAs
    k_integral<<<g1, 256>>>(fm);

    k_gather<<<NBOX, CC>>>(bboxes, out + RF_ELEMS);

    dim3 g4(2, NTOT/128);
    k_mma_gemm<<<g4, 256, GEMM_SMEM>>>(bias, out);
}

// round 6
// speedup vs baseline: 3.1875x; 1.0799x over previous
#include <cuda_runtime.h>
#include <cuda_fp16.h>
#include <math.h>
#include <stdint.h>

#define BB 8
#define CC 256
#define HFD 160
#define WFD 160
#define NN 128
#define SS 7
#define HP 161
#define NBOX (BB*NN)                       // 1024
#define NREG (SS*SS)                       // 49
#define NTOT (NBOX*NREG)                   // 50176
#define RF_ELEMS ((size_t)NBOX*CC*NREG)    // 12,845,056
#define SLAB 8
#define CSTR 164
#define NSTRIP 5
#define SROWS 32

// -------- scratch --------
__device__ float  g_I[(size_t)BB*HP*HP*CC];               // strip-LOCAL integrals [b][hp][wp][c]
__device__ float  g_P[(size_t)BB*NSTRIP*HP*CC];           // strip prefix offsets [b][s][wp][c]
__device__ __align__(16) __half g_regh[(size_t)NTOT*CC];  // region avgs fp16 [n][c]
__device__ __align__(16) __half g_Wh[CC*CC];              // W fp16 [o][c]

__device__ __forceinline__ uint32_t smem_u32(const void* p) {
    uint32_t a;
    asm("{ .reg .u64 t; cvta.to.shared.u64 t, %1; cvt.u32.u64 %0, t; }"
        : "=r"(a) : "l"(p));
    return a;
}

// ============================================================
// K0: W -> fp16
// ============================================================
__global__ void k_convw(const float* __restrict__ Wm) {
    int i = blockIdx.x * 256 + threadIdx.x;
    g_Wh[i] = __float2half_rn(Wm[i]);
}

// ============================================================
// K1a: strip-local 2D integral. CTA = (8-ch slab, strip, batch).
// Warp = one channel; 32-row serial loop; channel-last output.
// ============================================================
__global__ void __launch_bounds__(256) k_integral(const float* __restrict__ fm) {
    __shared__ float stg[2][SLAB*CSTR];
    const int b  = blockIdx.z;
    const int s  = blockIdx.y;
    const int c0 = blockIdx.x * SLAB;
    const int tid = threadIdx.x, w = tid >> 5, lane = tid & 31;
    const int c = c0 + w;

    const float* in  = fm + ((size_t)(b*CC + c)*HFD + s*SROWS)*WFD;
    float* outb = g_I + (((size_t)b*HP)*HP)*CC + c0;

    if (s == 0) {
        for (int idx = tid; idx < HP*SLAB; idx += 256) {
            int wp = idx >> 3, cc = idx & 7;
            outb[(size_t)wp*CC + cc] = 0.f;
        }
    }

    float colsum[5] = {0.f, 0.f, 0.f, 0.f, 0.f};
    float v[5];
    #pragma unroll
    for (int j = 0; j < 5; ++j) v[j] = in[j*32 + lane];

    for (int r = 0; r < SROWS; ++r) {
        float nv[5] = {0.f, 0.f, 0.f, 0.f, 0.f};
        if (r + 1 < SROWS) {
            #pragma unroll
            for (int j = 0; j < 5; ++j) nv[j] = in[(size_t)(r+1)*WFD + j*32 + lane];
        }

        #pragma unroll
        for (int off = 1; off < 32; off <<= 1) {
            #pragma unroll
            for (int j = 0; j < 5; ++j) {
                float n = __shfl_up_sync(0xffffffffu, v[j], off);
                if (lane >= off) v[j] += n;
            }
        }
        float pre = 0.f;
        #pragma unroll
        for (int j = 0; j < 5; ++j) {
            float tot = __shfl_sync(0xffffffffu, v[j], 31);
            v[j] += pre;
            pre += tot;
        }

        const int p = r & 1;
        #pragma unroll
        for (int j = 0; j < 5; ++j) {
            colsum[j] += v[j];
            stg[p][w*CSTR + j*32 + lane] = colsum[j];
        }
        __syncthreads();

        float* orow = outb + (size_t)(s*SROWS + r + 1)*HP*CC;
        for (int idx = tid; idx < HP*4; idx += 256) {
            int wp = idx >> 2, cp = idx & 3;
            float2 val;
            if (wp == 0) { val.x = 0.f; val.y = 0.f; }
            else {
                val.x = stg[p][(cp*2    )*CSTR + (wp-1)];
                val.y = stg[p][(cp*2 + 1)*CSTR + (wp-1)];
            }
            *(float2*)(orow + (size_t)wp*CC + cp*2) = val;
        }

        #pragma unroll
        for (int j = 0; j < 5; ++j) v[j] = nv[j];
    }
}

// ============================================================
// K1b: strip prefix P[b][s] = sum of strip totals below strip s.
// CTA = (wp, b), thread = c.
// ============================================================
__global__ void __launch_bounds__(256) k_strippfx() {
    const int b  = blockIdx.y;
    const int wp = blockIdx.x;
    const int c  = threadIdx.x;
    const float* I = g_I + (((size_t)b*HP)*HP + wp)*CC + c;
    float* P = g_P + (((size_t)b*NSTRIP)*HP + wp)*CC + c;
    P[0] = 0.f;
    float acc = 0.f;
    #pragma unroll
    for (int s = 1; s < NSTRIP; ++s) {
        acc += I[(size_t)(s*SROWS)*HP*CC];
        P[(size_t)s*HP*CC] = acc;
    }
}

// ============================================================
// K3: per-box corner gather + region average (fp16 out) + areas.
// Corner value = I_local[hp] + P[strip(hp)]  (both zero at hp==0).
// ============================================================
__global__ void k_gather(const float* __restrict__ bboxes,
                         float* __restrict__ out_area) {
    const int box = blockIdx.x;
    const int b   = box >> 7;
    const int c   = threadIdx.x;

    const float bx1 = bboxes[box*4+0];
    const float by1 = bboxes[box*4+1];
    const float bx2 = bboxes[box*4+2];
    const float by2 = bboxes[box*4+3];
    if (c == 0) out_area[box] = (bx2-bx1)*(by2-by1);

    int x1 = (int)floorf(bx1*0.25f); x1 = min(max(x1, 0), WFD-1);
    int y1 = (int)floorf(by1*0.25f); y1 = min(max(y1, 0), HFD-1);
    int x2 = (int)floorf(bx2*0.25f); x2 = min(max(x2, x1+1), WFD);
    int y2 = (int)floorf(by2*0.25f); y2 = min(max(y2, y1+1), HFD);
    const int Lx = x2 - x1, Ly = y2 - y1;

    int rs[SS], re[SS], cs[SS], ce[SS];
    #pragma unroll
    for (int i = 0; i < SS; ++i) {
        rs[i] = y1 + (i*Ly)/SS;
        re[i] = y1 + ((i+1)*Ly + SS-1)/SS;
        cs[i] = x1 + (i*Lx)/SS;
        ce[i] = x1 + ((i+1)*Lx + SS-1)/SS;
    }

    const float* I = g_I + (size_t)b*HP*HP*CC + c;
    const float* P = g_P + ((size_t)b*NSTRIP*HP)*CC + c;
    __half* outp = g_regh + (size_t)box*(NREG*CC) + c;

    #pragma unroll
    for (int i = 0; i < SS; ++i) {
        const int hpS = rs[i], hpE = re[i];
        const int sS = (hpS > 0) ? ((hpS-1) >> 5) : 0;
        const int sE = (hpE-1) >> 5;
        const float* rowS = I + (size_t)hpS*HP*CC;
        const float* rowE = I + (size_t)hpE*HP*CC;
        const float* PS = P + (size_t)sS*HP*CC;
        const float* PE = P + (size_t)sE*HP*CC;
        const float dh = (float)(hpE - hpS);
        #pragma unroll
        for (int j = 0; j < SS; ++j) {
            const size_t wS = (size_t)cs[j]*CC, wE = (size_t)ce[j]*CC;
            float tl = rowS[wS] + PS[wS];
            float tr = rowS[wE] + PS[wE];
            float bl = rowE[wS] + PE[wS];
            float br = rowE[wE] + PE[wE];
            float cnt = dh * (float)(ce[j]-cs[j]);
            outp[(i*SS+j)*CC] = __float2half_rn((br - tr - bl + tl) / cnt);
        }
    }
}

// ============================================================
// K4: mma.sync f16 GEMM, K chunked (4 x 64) with cp.async pipeline.
// D[128m x 128n] = Wh[m][k] @ Xh[n][k]^T + bias.  smem 66 KB -> 2 CTA/SM.
// ============================================================
#define AB_BUF 16384
#define B_OFF  32768
#define GEMM_SMEM 66048
#define STG_LD 129

__global__ void __launch_bounds__(256) k_mma_gemm(const float* __restrict__ bias,
                                                  float* __restrict__ out) {
    extern __shared__ char sm[];
    const uint32_t sb = smem_u32(sm);
    const int tid = threadIdx.x, wid = tid >> 5, lane = tid & 31;
    const int m0 = blockIdx.x * 128;
    const int n0 = blockIdx.y * 128;

    auto issue = [&](int kc, int p) {
        #pragma unroll
        for (int it = 0; it < 4; ++it) {
            int u = tid + it*256;
            int row = u >> 3, kb = u & 7;
            uint32_t off = (uint32_t)(row*128 + ((kb ^ (row & 7)) << 4));
            const __half* asrc = g_Wh   + (size_t)(m0 + row)*CC + kc*64 + kb*8;
            const __half* bsrc = g_regh + (size_t)(n0 + row)*CC + kc*64 + kb*8;
            uint32_t da = sb + p*AB_BUF + off;
            uint32_t db = sb + B_OFF + p*AB_BUF + off;
            asm volatile("cp.async.cg.shared.global [%0], [%1], 16;" :: "r"(da), "l"(asrc));
            asm volatile("cp.async.cg.shared.global [%0], [%1], 16;" :: "r"(db), "l"(bsrc));
        }
        asm volatile("cp.async.commit_group;");
    };

    const int wm = wid >> 2;
    const int wn = wid & 3;
    const int a_l15 = lane & 15;
    const int a_khi = lane >> 4;
    const int b_l7  = lane & 7;
    const int b_khi = (lane >> 3) & 1;

    uint32_t a_row[4], a_xr[4], b_row[4], b_xr[4];
    #pragma unroll
    for (int mf = 0; mf < 4; ++mf) {
        int mrow = wm*64 + mf*16 + a_l15;
        a_row[mf] = (uint32_t)(mrow*128);
        a_xr[mf] = (uint32_t)(mrow & 7);
    }
    #pragma unroll
    for (int nf = 0; nf < 4; ++nf) {
        int nrow = wn*32 + nf*8 + b_l7;
        b_row[nf] = (uint32_t)(nrow*128);
        b_xr[nf] = (uint32_t)(nrow & 7);
    }

    float acc[4][4][4];
    #pragma unroll
    for (int mf = 0; mf < 4; ++mf)
        #pragma unroll
        for (int nf = 0; nf < 4; ++nf)
            #pragma unroll
            for (int e = 0; e < 4; ++e) acc[mf][nf][e] = 0.f;

    issue(0, 0);

    #pragma unroll
    for (int kc = 0; kc < 4; ++kc) {
        const int p = kc & 1;
        if (kc < 3) {
            issue(kc+1, (kc+1) & 1);
            asm volatile("cp.async.wait_group 1;" ::: "memory");
        } else {
            asm volatile("cp.async.wait_group 0;" ::: "memory");
        }
        __syncthreads();

        #pragma unroll
        for (int ks = 0; ks < 4; ++ks) {
            uint32_t a[4][4], b[4][2];
            #pragma unroll
            for (int mf = 0; mf < 4; ++mf) {
                uint32_t kb = (uint32_t)(ks*2 + a_khi) ^ a_xr[mf];
                uint32_t addr = sb + p*AB_BUF + a_row[mf] + (kb << 4);
                asm volatile("ldmatrix.sync.aligned.m8n8.x4.shared.b16 {%0,%1,%2,%3}, [%4];"
                             : "=r"(a[mf][0]), "=r"(a[mf][1]), "=r"(a[mf][2]), "=r"(a[mf][3])
                             : "r"(addr));
            }
            #pragma unroll
            for (int nf = 0; nf < 4; ++nf) {
                uint32_t kb = (uint32_t)(ks*2 + b_khi) ^ b_xr[nf];
                uint32_t addr = sb + B_OFF + p*AB_BUF + b_row[nf] + (kb << 4);
                asm volatile("ldmatrix.sync.aligned.m8n8.x2.shared.b16 {%0,%1}, [%2];"
                             : "=r"(b[nf][0]), "=r"(b[nf][1])
                             : "r"(addr));
            }
            #pragma unroll
            for (int mf = 0; mf < 4; ++mf)
                #pragma unroll
                for (int nf = 0; nf < 4; ++nf) {
                    asm volatile(
                        "mma.sync.aligned.m16n8k16.row.col.f32.f16.f16.f32 "
                        "{%0,%1,%2,%3}, {%4,%5,%6,%7}, {%8,%9}, {%0,%1,%2,%3};"
                        : "+f"(acc[mf][nf][0]), "+f"(acc[mf][nf][1]),
                          "+f"(acc[mf][nf][2]), "+f"(acc[mf][nf][3])
                        : "r"(a[mf][0]), "r"(a[mf][1]), "r"(a[mf][2]), "r"(a[mf][3]),
                          "r"(b[nf][0]), "r"(b[nf][1]));
                }
        }
        __syncthreads();
    }

    // ---- stage f32 result into smem [128][129], then coalesced scatter ----
    float* stgf = (float*)sm;
    const int crow = lane >> 2;
    const int ccol = (lane & 3) * 2;
    #pragma unroll
    for (int mf = 0; mf < 4; ++mf) {
        int mr = wm*64 + mf*16 + crow;
        #pragma unroll
        for (int nf = 0; nf < 4; ++nf) {
            int nc = wn*32 + nf*8 + ccol;
            stgf[mr*STG_LD + nc]         = acc[mf][nf][0];
            stgf[mr*STG_LD + nc + 1]     = acc[mf][nf][1];
            stgf[(mr+8)*STG_LD + nc]     = acc[mf][nf][2];
            stgf[(mr+8)*STG_LD + nc + 1] = acc[mf][nf][3];
        }
    }
    __syncthreads();

    #pragma unroll 4
    for (int i = tid; i < 128*128; i += 256) {
        int m = i >> 7, n = i & 127;
        int nn = n0 + n, o = m0 + m;
        int box = nn / NREG, r = nn - box*NREG;
        out[(size_t)box*(CC*NREG) + (size_t)o*NREG + r] = stgf[m*STG_LD + n] + bias[o];
    }
}

// ============================================================
extern "C" void kernel_launch(void* const* d_in, const int* in_sizes, int n_in,
                              void* d_out, int out_size) {
    const float* fm     = (const float*)d_in[0];
    const float* bboxes = (const float*)d_in[1];
    const float* Wm     = (const float*)d_in[2];
    const float* bias   = (const float*)d_in[3];
    float* out = (float*)d_out;

    cudaFuncSetAttribute(k_mma_gemm, cudaFuncAttributeMaxDynamicSharedMemorySize,
                         GEMM_SMEM);

    k_convw<<<CC, 256>>>(Wm);

    dim3 g1(CC/SLAB, NSTRIP, BB);          // 32 x 5 x 8 = 1280 CTAs
    k_integral<<<g1, 256>>>(fm);

    dim3 gp(HP, BB);
    k_strippfx<<<gp, 256>>>();

    k_gather<<<NBOX, CC>>>(bboxes, out + RF_ELEMS);

    dim3 g4(2, NTOT/128);
    k_mma_gemm<<<g4, 256, GEMM_SMEM>>>(bias, out);
}

// round 7
// speedup vs baseline: 3.7682x; 1.1822x over previous
#include <cuda_runtime.h>
#include <cuda_fp16.h>
#include <math.h>
#include <stdint.h>

#define BB 8
#define CC 256
#define HFD 160
#define WFD 160
#define NN 128
#define SS 7
#define HP 161
#define NBOX (BB*NN)                       // 1024
#define NREG (SS*SS)                       // 49
#define NTOT (NBOX*NREG)                   // 50176
#define RF_ELEMS ((size_t)NBOX*CC*NREG)    // 12,845,056
#define SLAB 8
#define CSTR 164
#define NSTRIP 10
#define SROWS 16

// -------- scratch --------
__device__ float  g_I[(size_t)BB*HP*HP*CC];               // strip-LOCAL integrals [b][hp][wp][c]
__device__ float  g_P[(size_t)BB*NSTRIP*HP*CC];           // strip prefix offsets [b][s][wp][c]
__device__ __align__(16) __half g_regh[(size_t)NTOT*CC];  // region avgs fp16 [n][c]
__device__ __align__(16) __half g_Wh[CC*CC];              // W fp16 [o][c]

__device__ __forceinline__ uint32_t smem_u32(const void* p) {
    uint32_t a;
    asm("{ .reg .u64 t; cvta.to.shared.u64 t, %1; cvt.u32.u64 %0, t; }"
        : "=r"(a) : "l"(p));
    return a;
}

// ============================================================
// K0: W -> fp16
// ============================================================
__global__ void k_convw(const float* __restrict__ Wm) {
    int i = blockIdx.x * 256 + threadIdx.x;
    g_Wh[i] = __float2half_rn(Wm[i]);
}

// ============================================================
// K1a: strip-local 2D integral. CTA = (8-ch slab, strip, batch).
// Warp = one channel; 16-row serial loop; channel-last output.
// ============================================================
__global__ void __launch_bounds__(256) k_integral(const float* __restrict__ fm) {
    __shared__ float stg[2][SLAB*CSTR];
    const int b  = blockIdx.z;
    const int s  = blockIdx.y;
    const int c0 = blockIdx.x * SLAB;
    const int tid = threadIdx.x, w = tid >> 5, lane = tid & 31;
    const int c = c0 + w;

    const float* in  = fm + ((size_t)(b*CC + c)*HFD + s*SROWS)*WFD;
    float* outb = g_I + (((size_t)b*HP)*HP)*CC + c0;

    if (s == 0) {
        for (int idx = tid; idx < HP*SLAB; idx += 256) {
            int wp = idx >> 3, cc = idx & 7;
            outb[(size_t)wp*CC + cc] = 0.f;
        }
    }

    float colsum[5] = {0.f, 0.f, 0.f, 0.f, 0.f};
    float v[5];
    #pragma unroll
    for (int j = 0; j < 5; ++j) v[j] = in[j*32 + lane];

    for (int r = 0; r < SROWS; ++r) {
        float nv[5] = {0.f, 0.f, 0.f, 0.f, 0.f};
        if (r + 1 < SROWS) {
            #pragma unroll
            for (int j = 0; j < 5; ++j) nv[j] = in[(size_t)(r+1)*WFD + j*32 + lane];
        }

        #pragma unroll
        for (int off = 1; off < 32; off <<= 1) {
            #pragma unroll
            for (int j = 0; j < 5; ++j) {
                float n = __shfl_up_sync(0xffffffffu, v[j], off);
                if (lane >= off) v[j] += n;
            }
        }
        float pre = 0.f;
        #pragma unroll
        for (int j = 0; j < 5; ++j) {
            float tot = __shfl_sync(0xffffffffu, v[j], 31);
            v[j] += pre;
            pre += tot;
        }

        const int p = r & 1;
        #pragma unroll
        for (int j = 0; j < 5; ++j) {
            colsum[j] += v[j];
            stg[p][w*CSTR + j*32 + lane] = colsum[j];
        }
        __syncthreads();

        float* orow = outb + (size_t)(s*SROWS + r + 1)*HP*CC;
        for (int idx = tid; idx < HP*4; idx += 256) {
            int wp = idx >> 2, cp = idx & 3;
            float2 val;
            if (wp == 0) { val.x = 0.f; val.y = 0.f; }
            else {
                val.x = stg[p][(cp*2    )*CSTR + (wp-1)];
                val.y = stg[p][(cp*2 + 1)*CSTR + (wp-1)];
            }
            *(float2*)(orow + (size_t)wp*CC + cp*2) = val;
        }

        #pragma unroll
        for (int j = 0; j < 5; ++j) v[j] = nv[j];
    }
}

// ============================================================
// K1b: strip prefix P[b][s] = sum of strip totals below strip s.
// ============================================================
__global__ void __launch_bounds__(256) k_strippfx() {
    const int b  = blockIdx.y;
    const int wp = blockIdx.x;
    const int c  = threadIdx.x;
    const float* I = g_I + (((size_t)b*HP)*HP + wp)*CC + c;
    float* P = g_P + (((size_t)b*NSTRIP)*HP + wp)*CC + c;
    P[0] = 0.f;
    float acc = 0.f;
    #pragma unroll
    for (int s = 1; s < NSTRIP; ++s) {
        acc += I[(size_t)(s*SROWS)*HP*CC];
        P[(size_t)s*HP*CC] = acc;
    }
}

// ============================================================
// K3: corner gather + region average. CTA = (box, i-row); 7168 CTAs.
// Corner = I_local[hp] + P[strip(hp)] (both zero at hp==0).
// ============================================================
__global__ void __launch_bounds__(256) k_gather(const float* __restrict__ bboxes,
                                                float* __restrict__ out_area) {
    const int box = blockIdx.x;
    const int i   = blockIdx.y;          // region row 0..6
    const int b   = box >> 7;
    const int c   = threadIdx.x;

    const float bx1 = bboxes[box*4+0];
    const float by1 = bboxes[box*4+1];
    const float bx2 = bboxes[box*4+2];
    const float by2 = bboxes[box*4+3];
    if (i == 0 && c == 0) out_area[box] = (bx2-bx1)*(by2-by1);

    int x1 = (int)floorf(bx1*0.25f); x1 = min(max(x1, 0), WFD-1);
    int y1 = (int)floorf(by1*0.25f); y1 = min(max(y1, 0), HFD-1);
    int x2 = (int)floorf(bx2*0.25f); x2 = min(max(x2, x1+1), WFD);
    int y2 = (int)floorf(by2*0.25f); y2 = min(max(y2, y1+1), HFD);
    const int Lx = x2 - x1, Ly = y2 - y1;

    const int hpS = y1 + (i*Ly)/SS;
    const int hpE = y1 + ((i+1)*Ly + SS-1)/SS;

    int cs[SS], ce[SS];
    #pragma unroll
    for (int j = 0; j < SS; ++j) {
        cs[j] = x1 + (j*Lx)/SS;
        ce[j] = x1 + ((j+1)*Lx + SS-1)/SS;
    }

    const float* I = g_I + (size_t)b*HP*HP*CC + c;
    const float* P = g_P + ((size_t)b*NSTRIP*HP)*CC + c;

    const int sS = (hpS > 0) ? ((hpS-1) >> 4) : 0;
    const int sE = (hpE-1) >> 4;
    const float* rowS = I + (size_t)hpS*HP*CC;
    const float* rowE = I + (size_t)hpE*HP*CC;
    const float* PS = P + (size_t)sS*HP*CC;
    const float* PE = P + (size_t)sE*HP*CC;
    const float dh = (float)(hpE - hpS);

    __half* outp = g_regh + (size_t)box*(NREG*CC) + i*SS*CC + c;

    #pragma unroll
    for (int j = 0; j < SS; ++j) {
        const size_t wS = (size_t)cs[j]*CC, wE = (size_t)ce[j]*CC;
        float tl = rowS[wS] + PS[wS];
        float tr = rowS[wE] + PS[wE];
        float bl = rowE[wS] + PE[wS];
        float br = rowE[wE] + PE[wE];
        float cnt = dh * (float)(ce[j]-cs[j]);
        outp[j*CC] = __float2half_rn((br - tr - bl + tl) / cnt);
    }
}

// ============================================================
// K4: mma.sync f16 GEMM, K chunked (4 x 64) with cp.async pipeline.
// ============================================================
#define AB_BUF 16384
#define B_OFF  32768
#define GEMM_SMEM 66048
#define STG_LD 129

__global__ void __launch_bounds__(256) k_mma_gemm(const float* __restrict__ bias,
                                                  float* __restrict__ out) {
    extern __shared__ char sm[];
    const uint32_t sb = smem_u32(sm);
    const int tid = threadIdx.x, wid = tid >> 5, lane = tid & 31;
    const int m0 = blockIdx.x * 128;
    const int n0 = blockIdx.y * 128;

    auto issue = [&](int kc, int p) {
        #pragma unroll
        for (int it = 0; it < 4; ++it) {
            int u = tid + it*256;
            int row = u >> 3, kb = u & 7;
            uint32_t off = (uint32_t)(row*128 + ((kb ^ (row & 7)) << 4));
            const __half* asrc = g_Wh   + (size_t)(m0 + row)*CC + kc*64 + kb*8;
            const __half* bsrc = g_regh + (size_t)(n0 + row)*CC + kc*64 + kb*8;
            uint32_t da = sb + p*AB_BUF + off;
            uint32_t db = sb + B_OFF + p*AB_BUF + off;
            asm volatile("cp.async.cg.shared.global [%0], [%1], 16;" :: "r"(da), "l"(asrc));
            asm volatile("cp.async.cg.shared.global [%0], [%1], 16;" :: "r"(db), "l"(bsrc));
        }
        asm volatile("cp.async.commit_group;");
    };

    const int wm = wid >> 2;
    const int wn = wid & 3;
    const int a_l15 = lane & 15;
    const int a_khi = lane >> 4;
    const int b_l7  = lane & 7;
    const int b_khi = (lane >> 3) & 1;

    uint32_t a_row[4], a_xr[4], b_row[4], b_xr[4];
    #pragma unroll
    for (int mf = 0; mf < 4; ++mf) {
        int mrow = wm*64 + mf*16 + a_l15;
        a_row[mf] = (uint32_t)(mrow*128);
        a_xr[mf] = (uint32_t)(mrow & 7);
    }
    #pragma unroll
    for (int nf = 0; nf < 4; ++nf) {
        int nrow = wn*32 + nf*8 + b_l7;
        b_row[nf] = (uint32_t)(nrow*128);
        b_xr[nf] = (uint32_t)(nrow & 7);
    }

    float acc[4][4][4];
    #pragma unroll
    for (int mf = 0; mf < 4; ++mf)
        #pragma unroll
        for (int nf = 0; nf < 4; ++nf)
            #pragma unroll
            for (int e = 0; e < 4; ++e) acc[mf][nf][e] = 0.f;

    issue(0, 0);

    #pragma unroll
    for (int kc = 0; kc < 4; ++kc) {
        const int p = kc & 1;
        if (kc < 3) {
            issue(kc+1, (kc+1) & 1);
            asm volatile("cp.async.wait_group 1;" ::: "memory");
        } else {
            asm volatile("cp.async.wait_group 0;" ::: "memory");
        }
        __syncthreads();

        #pragma unroll
        for (int ks = 0; ks < 4; ++ks) {
            uint32_t a[4][4], b[4][2];
            #pragma unroll
            for (int mf = 0; mf < 4; ++mf) {
                uint32_t kb = (uint32_t)(ks*2 + a_khi) ^ a_xr[mf];
                uint32_t addr = sb + p*AB_BUF + a_row[mf] + (kb << 4);
                asm volatile("ldmatrix.sync.aligned.m8n8.x4.shared.b16 {%0,%1,%2,%3}, [%4];"
                             : "=r"(a[mf][0]), "=r"(a[mf][1]), "=r"(a[mf][2]), "=r"(a[mf][3])
                             : "r"(addr));
            }
            #pragma unroll
            for (int nf = 0; nf < 4; ++nf) {
                uint32_t kb = (uint32_t)(ks*2 + b_khi) ^ b_xr[nf];
                uint32_t addr = sb + B_OFF + p*AB_BUF + b_row[nf] + (kb << 4);
                asm volatile("ldmatrix.sync.aligned.m8n8.x2.shared.b16 {%0,%1}, [%2];"
                             : "=r"(b[nf][0]), "=r"(b[nf][1])
                             : "r"(addr));
            }
            #pragma unroll
            for (int mf = 0; mf < 4; ++mf)
                #pragma unroll
                for (int nf = 0; nf < 4; ++nf) {
                    asm volatile(
                        "mma.sync.aligned.m16n8k16.row.col.f32.f16.f16.f32 "
                        "{%0,%1,%2,%3}, {%4,%5,%6,%7}, {%8,%9}, {%0,%1,%2,%3};"
                        : "+f"(acc[mf][nf][0]), "+f"(acc[mf][nf][1]),
                          "+f"(acc[mf][nf][2]), "+f"(acc[mf][nf][3])
                        : "r"(a[mf][0]), "r"(a[mf][1]), "r"(a[mf][2]), "r"(a[mf][3]),
                          "r"(b[nf][0]), "r"(b[nf][1]));
                }
        }
        __syncthreads();
    }

    float* stgf = (float*)sm;
    const int crow = lane >> 2;
    const int ccol = (lane & 3) * 2;
    #pragma unroll
    for (int mf = 0; mf < 4; ++mf) {
        int mr = wm*64 + mf*16 + crow;
        #pragma unroll
        for (int nf = 0; nf < 4; ++nf) {
            int nc = wn*32 + nf*8 + ccol;
            stgf[mr*STG_LD + nc]         = acc[mf][nf][0];
            stgf[mr*STG_LD + nc + 1]     = acc[mf][nf][1];
            stgf[(mr+8)*STG_LD + nc]     = acc[mf][nf][2];
            stgf[(mr+8)*STG_LD + nc + 1] = acc[mf][nf][3];
        }
    }
    __syncthreads();

    #pragma unroll 4
    for (int i = tid; i < 128*128; i += 256) {
        int m = i >> 7, n = i & 127;
        int nn = n0 + n, o = m0 + m;
        int box = nn / NREG, r = nn - box*NREG;
        out[(size_t)box*(CC*NREG) + (size_t)o*NREG + r] = stgf[m*STG_LD + n] + bias[o];
    }
}

// ============================================================
extern "C" void kernel_launch(void* const* d_in, const int* in_sizes, int n_in,
                              void* d_out, int out_size) {
    const float* fm     = (const float*)d_in[0];
    const float* bboxes = (const float*)d_in[1];
    const float* Wm     = (const float*)d_in[2];
    const float* bias   = (const float*)d_in[3];
    float* out = (float*)d_out;

    cudaFuncSetAttribute(k_mma_gemm, cudaFuncAttributeMaxDynamicSharedMemorySize,
                         GEMM_SMEM);

    k_convw<<<CC, 256>>>(Wm);

    dim3 g1(CC/SLAB, NSTRIP, BB);          // 32 x 10 x 8 = 2560 CTAs
    k_integral<<<g1, 256>>>(fm);

    dim3 gp(HP, BB);
    k_strippfx<<<gp, 256>>>();

    dim3 g3(NBOX, SS);                     // 1024 x 7
    k_gather<<<g3, 256>>>(bboxes, out + RF_ELEMS);

    dim3 g4(2, NTOT/128);
    k_mma_gemm<<<g4, 256, GEMM_SMEM>>>(bias, out);
}

// round 8
// speedup vs baseline: 3.9057x; 1.0365x over previous
#include <cuda_runtime.h>
#include <cuda_fp16.h>
#include <math.h>
#include <stdint.h>

#define BB 8
#define CC 256
#define HFD 160
#define WFD 160
#define NN 128
#define SS 7
#define HP 161
#define NBOX (BB*NN)                       // 1024
#define NREG (SS*SS)                       // 49
#define NTOT (NBOX*NREG)                   // 50176
#define RF_ELEMS ((size_t)NBOX*CC*NREG)    // 12,845,056
#define SLAB 8
#define CSTR 164
#define NSTRIP 20
#define SROWS 8

// -------- scratch --------
__device__ float  g_I[(size_t)BB*HP*HP*CC];               // strip-LOCAL integrals [b][hp][wp][c]
__device__ float  g_P[(size_t)BB*NSTRIP*HP*CC];           // strip prefix offsets [b][s][wp][c]
__device__ __align__(16) __half g_regh[(size_t)NTOT*CC];  // region avgs fp16 [n][c]
__device__ __align__(16) __half g_Wh[CC*CC];              // W fp16 [o][c]

__device__ __forceinline__ uint32_t smem_u32(const void* p) {
    uint32_t a;
    asm("{ .reg .u64 t; cvta.to.shared.u64 t, %1; cvt.u32.u64 %0, t; }"
        : "=r"(a) : "l"(p));
    return a;
}

// ============================================================
// K0: W -> fp16
// ============================================================
__global__ void k_convw(const float* __restrict__ Wm) {
    int i = blockIdx.x * 256 + threadIdx.x;
    g_Wh[i] = __float2half_rn(Wm[i]);
}

// ============================================================
// K1a: strip-local 2D integral. CTA = (8-ch slab, strip, batch).
// Warp = one channel; 8-row serial loop; channel-last output.
// ============================================================
__global__ void __launch_bounds__(256) k_integral(const float* __restrict__ fm) {
    __shared__ float stg[2][SLAB*CSTR];
    const int b  = blockIdx.z;
    const int s  = blockIdx.y;
    const int c0 = blockIdx.x * SLAB;
    const int tid = threadIdx.x, w = tid >> 5, lane = tid & 31;
    const int c = c0 + w;

    const float* in  = fm + ((size_t)(b*CC + c)*HFD + s*SROWS)*WFD;
    float* outb = g_I + (((size_t)b*HP)*HP)*CC + c0;

    if (s == 0) {
        for (int idx = tid; idx < HP*SLAB; idx += 256) {
            int wp = idx >> 3, cc = idx & 7;
            outb[(size_t)wp*CC + cc] = 0.f;
        }
    }

    float colsum[5] = {0.f, 0.f, 0.f, 0.f, 0.f};
    float v[5];
    #pragma unroll
    for (int j = 0; j < 5; ++j) v[j] = in[j*32 + lane];

    #pragma unroll
    for (int r = 0; r < SROWS; ++r) {
        float nv[5] = {0.f, 0.f, 0.f, 0.f, 0.f};
        if (r + 1 < SROWS) {
            #pragma unroll
            for (int j = 0; j < 5; ++j) nv[j] = in[(size_t)(r+1)*WFD + j*32 + lane];
        }

        #pragma unroll
        for (int off = 1; off < 32; off <<= 1) {
            #pragma unroll
            for (int j = 0; j < 5; ++j) {
                float n = __shfl_up_sync(0xffffffffu, v[j], off);
                if (lane >= off) v[j] += n;
            }
        }
        float pre = 0.f;
        #pragma unroll
        for (int j = 0; j < 5; ++j) {
            float tot = __shfl_sync(0xffffffffu, v[j], 31);
            v[j] += pre;
            pre += tot;
        }

        const int p = r & 1;
        #pragma unroll
        for (int j = 0; j < 5; ++j) {
            colsum[j] += v[j];
            stg[p][w*CSTR + j*32 + lane] = colsum[j];
        }
        __syncthreads();

        float* orow = outb + (size_t)(s*SROWS + r + 1)*HP*CC;
        for (int idx = tid; idx < HP*4; idx += 256) {
            int wp = idx >> 2, cp = idx & 3;
            float2 val;
            if (wp == 0) { val.x = 0.f; val.y = 0.f; }
            else {
                val.x = stg[p][(cp*2    )*CSTR + (wp-1)];
                val.y = stg[p][(cp*2 + 1)*CSTR + (wp-1)];
            }
            *(float2*)(orow + (size_t)wp*CC + cp*2) = val;
        }

        #pragma unroll
        for (int j = 0; j < 5; ++j) v[j] = nv[j];
    }
}

// ============================================================
// K1b: strip prefix P[b][s] = sum of strip totals below strip s.
// ============================================================
__global__ void __launch_bounds__(256) k_strippfx() {
    const int b  = blockIdx.y;
    const int wp = blockIdx.x;
    const int c  = threadIdx.x;
    const float* I = g_I + (((size_t)b*HP)*HP + wp)*CC + c;
    float* P = g_P + (((size_t)b*NSTRIP)*HP + wp)*CC + c;
    P[0] = 0.f;
    float acc = 0.f;
    #pragma unroll
    for (int s = 1; s < NSTRIP; ++s) {
        acc += I[(size_t)(s*SROWS)*HP*CC];
        P[(size_t)s*HP*CC] = acc;
    }
}

// ============================================================
// K3: corner gather, float2 loads / half2 stores.
// CTA = (box, i-row); 128 threads (thread = channel pair).
// Corner = I_local[hp] + P[strip(hp)] (both zero at hp==0).
// ============================================================
__global__ void __launch_bounds__(128) k_gather(const float* __restrict__ bboxes,
                                                float* __restrict__ out_area) {
    const int box = blockIdx.x;
    const int i   = blockIdx.y;
    const int b   = box >> 7;
    const int t   = threadIdx.x;           // channel pair 0..127

    const float bx1 = bboxes[box*4+0];
    const float by1 = bboxes[box*4+1];
    const float bx2 = bboxes[box*4+2];
    const float by2 = bboxes[box*4+3];
    if (i == 0 && t == 0) out_area[box] = (bx2-bx1)*(by2-by1);

    int x1 = (int)floorf(bx1*0.25f); x1 = min(max(x1, 0), WFD-1);
    int y1 = (int)floorf(by1*0.25f); y1 = min(max(y1, 0), HFD-1);
    int x2 = (int)floorf(bx2*0.25f); x2 = min(max(x2, x1+1), WFD);
    int y2 = (int)floorf(by2*0.25f); y2 = min(max(y2, y1+1), HFD);
    const int Lx = x2 - x1, Ly = y2 - y1;

    const int hpS = y1 + (i*Ly)/SS;
    const int hpE = y1 + ((i+1)*Ly + SS-1)/SS;

    int cs[SS], ce[SS];
    #pragma unroll
    for (int j = 0; j < SS; ++j) {
        cs[j] = x1 + (j*Lx)/SS;
        ce[j] = x1 + ((j+1)*Lx + SS-1)/SS;
    }

    // float2 units: plane row stride = HP*128 float2
    const float2* I2 = (const float2*)g_I + (size_t)b*HP*HP*128 + t;
    const float2* P2 = (const float2*)g_P + (size_t)b*NSTRIP*HP*128 + t;

    const int sS = (hpS > 0) ? ((hpS-1) >> 3) : 0;
    const int sE = (hpE-1) >> 3;
    const float2* rowS = I2 + (size_t)hpS*HP*128;
    const float2* rowE = I2 + (size_t)hpE*HP*128;
    const float2* PS = P2 + (size_t)sS*HP*128;
    const float2* PE = P2 + (size_t)sE*HP*128;
    const float inv_dh = 1.f / (float)(hpE - hpS);

    __half2* outp = (__half2*)(g_regh + (size_t)box*(NREG*CC) + i*SS*CC) + t;

    #pragma unroll
    for (int j = 0; j < SS; ++j) {
        const int wS = cs[j]*128, wE = ce[j]*128;
        float2 tl = rowS[wS], tr = rowS[wE];
        float2 bl = rowE[wS], br = rowE[wE];
        float2 ptl = PS[wS], ptr_ = PS[wE];
        float2 pbl = PE[wS], pbr = PE[wE];
        float inv = inv_dh / (float)(ce[j]-cs[j]);
        float vx = ((br.x + pbr.x) - (tr.x + ptr_.x) - (bl.x + pbl.x) + (tl.x + ptl.x)) * inv;
        float vy = ((br.y + pbr.y) - (tr.y + ptr_.y) - (bl.y + pbl.y) + (tl.y + ptl.y)) * inv;
        outp[j*128] = __floats2half2_rn(vx, vy);
    }
}

// ============================================================
// K4: mma.sync f16 GEMM, K chunked (4 x 64) with cp.async pipeline.
// ============================================================
#define AB_BUF 16384
#define B_OFF  32768
#define GEMM_SMEM 66048
#define STG_LD 129

__global__ void __launch_bounds__(256) k_mma_gemm(const float* __restrict__ bias,
                                                  float* __restrict__ out) {
    extern __shared__ char sm[];
    const uint32_t sb = smem_u32(sm);
    const int tid = threadIdx.x, wid = tid >> 5, lane = tid & 31;
    const int m0 = blockIdx.x * 128;
    const int n0 = blockIdx.y * 128;

    auto issue = [&](int kc, int p) {
        #pragma unroll
        for (int it = 0; it < 4; ++it) {
            int u = tid + it*256;
            int row = u >> 3, kb = u & 7;
            uint32_t off = (uint32_t)(row*128 + ((kb ^ (row & 7)) << 4));
            const __half* asrc = g_Wh   + (size_t)(m0 + row)*CC + kc*64 + kb*8;
            const __half* bsrc = g_regh + (size_t)(n0 + row)*CC + kc*64 + kb*8;
            uint32_t da = sb + p*AB_BUF + off;
            uint32_t db = sb + B_OFF + p*AB_BUF + off;
            asm volatile("cp.async.cg.shared.global [%0], [%1], 16;" :: "r"(da), "l"(asrc));
            asm volatile("cp.async.cg.shared.global [%0], [%1], 16;" :: "r"(db), "l"(bsrc));
        }
        asm volatile("cp.async.commit_group;");
    };

    const int wm = wid >> 2;
    const int wn = wid & 3;
    const int a_l15 = lane & 15;
    const int a_khi = lane >> 4;
    const int b_l7  = lane & 7;
    const int b_khi = (lane >> 3) & 1;

    uint32_t a_row[4], a_xr[4], b_row[4], b_xr[4];
    #pragma unroll
    for (int mf = 0; mf < 4; ++mf) {
        int mrow = wm*64 + mf*16 + a_l15;
        a_row[mf] = (uint32_t)(mrow*128);
        a_xr[mf] = (uint32_t)(mrow & 7);
    }
    #pragma unroll
    for (int nf = 0; nf < 4; ++nf) {
        int nrow = wn*32 + nf*8 + b_l7;
        b_row[nf] = (uint32_t)(nrow*128);
        b_xr[nf] = (uint32_t)(nrow & 7);
    }

    float acc[4][4][4];
    #pragma unroll
    for (int mf = 0; mf < 4; ++mf)
        #pragma unroll
        for (int nf = 0; nf < 4; ++nf)
            #pragma unroll
            for (int e = 0; e < 4; ++e) acc[mf][nf][e] = 0.f;

    issue(0, 0);

    #pragma unroll
    for (int kc = 0; kc < 4; ++kc) {
        const int p = kc & 1;
        if (kc < 3) {
            issue(kc+1, (kc+1) & 1);
            asm volatile("cp.async.wait_group 1;" ::: "memory");
        } else {
            asm volatile("cp.async.wait_group 0;" ::: "memory");
        }
        __syncthreads();

        #pragma unroll
        for (int ks = 0; ks < 4; ++ks) {
            uint32_t a[4][4], b[4][2];
            #pragma unroll
            for (int mf = 0; mf < 4; ++mf) {
                uint32_t kb = (uint32_t)(ks*2 + a_khi) ^ a_xr[mf];
                uint32_t addr = sb + p*AB_BUF + a_row[mf] + (kb << 4);
                asm volatile("ldmatrix.sync.aligned.m8n8.x4.shared.b16 {%0,%1,%2,%3}, [%4];"
                             : "=r"(a[mf][0]), "=r"(a[mf][1]), "=r"(a[mf][2]), "=r"(a[mf][3])
                             : "r"(addr));
            }
            #pragma unroll
            for (int nf = 0; nf < 4; ++nf) {
                uint32_t kb = (uint32_t)(ks*2 + b_khi) ^ b_xr[nf];
                uint32_t addr = sb + B_OFF + p*AB_BUF + b_row[nf] + (kb << 4);
                asm volatile("ldmatrix.sync.aligned.m8n8.x2.shared.b16 {%0,%1}, [%2];"
                             : "=r"(b[nf][0]), "=r"(b[nf][1])
                             : "r"(addr));
            }
            #pragma unroll
            for (int mf = 0; mf < 4; ++mf)
                #pragma unroll
                for (int nf = 0; nf < 4; ++nf) {
                    asm volatile(
                        "mma.sync.aligned.m16n8k16.row.col.f32.f16.f16.f32 "
                        "{%0,%1,%2,%3}, {%4,%5,%6,%7}, {%8,%9}, {%0,%1,%2,%3};"
                        : "+f"(acc[mf][nf][0]), "+f"(acc[mf][nf][1]),
                          "+f"(acc[mf][nf][2]), "+f"(acc[mf][nf][3])
                        : "r"(a[mf][0]), "r"(a[mf][1]), "r"(a[mf][2]), "r"(a[mf][3]),
                          "r"(b[nf][0]), "r"(b[nf][1]));
                }
        }
        __syncthreads();
    }

    float* stgf = (float*)sm;
    const int crow = lane >> 2;
    const int ccol = (lane & 3) * 2;
    #pragma unroll
    for (int mf = 0; mf < 4; ++mf) {
        int mr = wm*64 + mf*16 + crow;
        #pragma unroll
        for (int nf = 0; nf < 4; ++nf) {
            int nc = wn*32 + nf*8 + ccol;
            stgf[mr*STG_LD + nc]         = acc[mf][nf][0];
            stgf[mr*STG_LD + nc + 1]     = acc[mf][nf][1];
            stgf[(mr+8)*STG_LD + nc]     = acc[mf][nf][2];
            stgf[(mr+8)*STG_LD + nc + 1] = acc[mf][nf][3];
        }
    }
    __syncthreads();

    #pragma unroll 4
    for (int i = tid; i < 128*128; i += 256) {
        int m = i >> 7, n = i & 127;
        int nn = n0 + n, o = m0 + m;
        int box = nn / NREG, r = nn - box*NREG;
        out[(size_t)box*(CC*NREG) + (size_t)o*NREG + r] = stgf[m*STG_LD + n] + bias[o];
    }
}

// ============================================================
extern "C" void kernel_launch(void* const* d_in, const int* in_sizes, int n_in,
                              void* d_out, int out_size) {
    const float* fm     = (const float*)d_in[0];
    const float* bboxes = (const float*)d_in[1];
    const float* Wm     = (const float*)d_in[2];
    const float* bias   = (const float*)d_in[3];
    float* out = (float*)d_out;

    cudaFuncSetAttribute(k_mma_gemm, cudaFuncAttributeMaxDynamicSharedMemorySize,
                         GEMM_SMEM);

    k_convw<<<CC, 256>>>(Wm);

    dim3 g1(CC/SLAB, NSTRIP, BB);          // 32 x 20 x 8 = 5120 CTAs
    k_integral<<<g1, 256>>>(fm);

    dim3 gp(HP, BB);
    k_strippfx<<<gp, 256>>>();

    dim3 g3(NBOX, SS);                     // 1024 x 7
    k_gather<<<g3, 128>>>(bboxes, out + RF_ELEMS);

    dim3 g4(2, NTOT/128);
    k_mma_gemm<<<g4, 256, GEMM_SMEM>>>(bias, out);
}

// round 9
// speedup vs baseline: 3.9896x; 1.0215x over previous
#include <cuda_runtime.h>
#include <cuda_fp16.h>
#include <math.h>
#include <stdint.h>

#define BB 8
#define CC 256
#define HFD 160
#define WFD 160
#define NN 128
#define SS 7
#define HP 161
#define NBOX (BB*NN)                       // 1024
#define NREG (SS*SS)                       // 49
#define NTOT (NBOX*NREG)                   // 50176
#define RF_ELEMS ((size_t)NBOX*CC*NREG)    // 12,845,056
#define SLAB 8
#define CSTR 164
#define NSTRIP 20
#define SROWS 8

// -------- scratch --------
__device__ float  g_I[(size_t)BB*HP*HP*CC];               // strip-LOCAL integrals [b][hp][wp][c]
__device__ float  g_P[(size_t)BB*NSTRIP*HP*CC];           // strip prefix offsets [b][s][wp][c]
__device__ __align__(16) __half g_regh[(size_t)NTOT*CC];  // region avgs fp16 [n][c]
__device__ __align__(16) __half g_Wh[CC*CC];              // W fp16 [o][c]

__device__ __forceinline__ uint32_t smem_u32(const void* p) {
    uint32_t a;
    asm("{ .reg .u64 t; cvta.to.shared.u64 t, %1; cvt.u32.u64 %0, t; }"
        : "=r"(a) : "l"(p));
    return a;
}

// ============================================================
// K0: W -> fp16
// ============================================================
__global__ void k_convw(const float* __restrict__ Wm) {
    int i = blockIdx.x * 256 + threadIdx.x;
    g_Wh[i] = __float2half_rn(Wm[i]);
}

// ============================================================
// K1a: strip-local 2D integral. CTA = (8-ch slab, strip, batch).
// ============================================================
__global__ void __launch_bounds__(256) k_integral(const float* __restrict__ fm) {
    __shared__ float stg[2][SLAB*CSTR];
    const int b  = blockIdx.z;
    const int s  = blockIdx.y;
    const int c0 = blockIdx.x * SLAB;
    const int tid = threadIdx.x, w = tid >> 5, lane = tid & 31;
    const int c = c0 + w;

    const float* in  = fm + ((size_t)(b*CC + c)*HFD + s*SROWS)*WFD;
    float* outb = g_I + (((size_t)b*HP)*HP)*CC + c0;

    if (s == 0) {
        for (int idx = tid; idx < HP*SLAB; idx += 256) {
            int wp = idx >> 3, cc = idx & 7;
            outb[(size_t)wp*CC + cc] = 0.f;
        }
    }

    float colsum[5] = {0.f, 0.f, 0.f, 0.f, 0.f};
    float v[5];
    #pragma unroll
    for (int j = 0; j < 5; ++j) v[j] = in[j*32 + lane];

    #pragma unroll
    for (int r = 0; r < SROWS; ++r) {
        float nv[5] = {0.f, 0.f, 0.f, 0.f, 0.f};
        if (r + 1 < SROWS) {
            #pragma unroll
            for (int j = 0; j < 5; ++j) nv[j] = in[(size_t)(r+1)*WFD + j*32 + lane];
        }

        #pragma unroll
        for (int off = 1; off < 32; off <<= 1) {
            #pragma unroll
            for (int j = 0; j < 5; ++j) {
                float n = __shfl_up_sync(0xffffffffu, v[j], off);
                if (lane >= off) v[j] += n;
            }
        }
        float pre = 0.f;
        #pragma unroll
        for (int j = 0; j < 5; ++j) {
            float tot = __shfl_sync(0xffffffffu, v[j], 31);
            v[j] += pre;
            pre += tot;
        }

        const int p = r & 1;
        #pragma unroll
        for (int j = 0; j < 5; ++j) {
            colsum[j] += v[j];
            stg[p][w*CSTR + j*32 + lane] = colsum[j];
        }
        __syncthreads();

        float* orow = outb + (size_t)(s*SROWS + r + 1)*HP*CC;
        for (int idx = tid; idx < HP*4; idx += 256) {
            int wp = idx >> 2, cp = idx & 3;
            float2 val;
            if (wp == 0) { val.x = 0.f; val.y = 0.f; }
            else {
                val.x = stg[p][(cp*2    )*CSTR + (wp-1)];
                val.y = stg[p][(cp*2 + 1)*CSTR + (wp-1)];
            }
            *(float2*)(orow + (size_t)wp*CC + cp*2) = val;
        }

        #pragma unroll
        for (int j = 0; j < 5; ++j) v[j] = nv[j];
    }
}

// ============================================================
// K1b: strip prefix P[b][s] = sum of strip totals below strip s.
// ============================================================
__global__ void __launch_bounds__(256) k_strippfx() {
    const int b  = blockIdx.y;
    const int wp = blockIdx.x;
    const int c  = threadIdx.x;
    const float* I = g_I + (((size_t)b*HP)*HP + wp)*CC + c;
    float* P = g_P + (((size_t)b*NSTRIP)*HP + wp)*CC + c;
    P[0] = 0.f;
    float acc = 0.f;
    #pragma unroll
    for (int s = 1; s < NSTRIP; ++s) {
        acc += I[(size_t)(s*SROWS)*HP*CC];
        P[(size_t)s*HP*CC] = acc;
    }
}

// ============================================================
// K3: corner gather, float4 loads / 8-B half stores.
// CTA = (box, i-row); 64 threads (thread = channel quad).
// ============================================================
__global__ void __launch_bounds__(64) k_gather(const float* __restrict__ bboxes,
                                               float* __restrict__ out_area) {
    const int box = blockIdx.x;
    const int i   = blockIdx.y;
    const int b   = box >> 7;
    const int t   = threadIdx.x;           // channel quad 0..63

    const float bx1 = bboxes[box*4+0];
    const float by1 = bboxes[box*4+1];
    const float bx2 = bboxes[box*4+2];
    const float by2 = bboxes[box*4+3];
    if (i == 0 && t == 0) out_area[box] = (bx2-bx1)*(by2-by1);

    int x1 = (int)floorf(bx1*0.25f); x1 = min(max(x1, 0), WFD-1);
    int y1 = (int)floorf(by1*0.25f); y1 = min(max(y1, 0), HFD-1);
    int x2 = (int)floorf(bx2*0.25f); x2 = min(max(x2, x1+1), WFD);
    int y2 = (int)floorf(by2*0.25f); y2 = min(max(y2, y1+1), HFD);
    const int Lx = x2 - x1, Ly = y2 - y1;

    const int hpS = y1 + (i*Ly)/SS;
    const int hpE = y1 + ((i+1)*Ly + SS-1)/SS;

    int cs[SS], ce[SS];
    #pragma unroll
    for (int j = 0; j < SS; ++j) {
        cs[j] = x1 + (j*Lx)/SS;
        ce[j] = x1 + ((j+1)*Lx + SS-1)/SS;
    }

    // float4 units: plane row stride = HP*64 float4
    const float4* I4 = (const float4*)g_I + (size_t)b*HP*HP*64 + t;
    const float4* P4 = (const float4*)g_P + (size_t)b*NSTRIP*HP*64 + t;

    const int sS = (hpS > 0) ? ((hpS-1) >> 3) : 0;
    const int sE = (hpE-1) >> 3;
    const float4* rowS = I4 + (size_t)hpS*HP*64;
    const float4* rowE = I4 + (size_t)hpE*HP*64;
    const float4* PS = P4 + (size_t)sS*HP*64;
    const float4* PE = P4 + (size_t)sE*HP*64;
    const float inv_dh = 1.f / (float)(hpE - hpS);

    __half2* outp = (__half2*)(g_regh + (size_t)box*(NREG*CC) + i*SS*CC) + 2*t;

    #pragma unroll
    for (int j = 0; j < SS; ++j) {
        const int wS = cs[j]*64, wE = ce[j]*64;
        float4 tl = rowS[wS], tr = rowS[wE];
        float4 bl = rowE[wS], br = rowE[wE];
        float4 ptl = PS[wS], ptr_ = PS[wE];
        float4 pbl = PE[wS], pbr = PE[wE];
        float inv = inv_dh / (float)(ce[j]-cs[j]);
        float vx = ((br.x + pbr.x) - (tr.x + ptr_.x) - (bl.x + pbl.x) + (tl.x + ptl.x)) * inv;
        float vy = ((br.y + pbr.y) - (tr.y + ptr_.y) - (bl.y + pbl.y) + (tl.y + ptl.y)) * inv;
        float vz = ((br.z + pbr.z) - (tr.z + ptr_.z) - (bl.z + pbl.z) + (tl.z + ptl.z)) * inv;
        float vw = ((br.w + pbr.w) - (tr.w + ptr_.w) - (bl.w + pbl.w) + (tl.w + ptl.w)) * inv;
        __half2 h0 = __floats2half2_rn(vx, vy);
        __half2 h1 = __floats2half2_rn(vz, vw);
        uint2 pk;
        pk.x = *(uint32_t*)&h0;
        pk.y = *(uint32_t*)&h1;
        *(uint2*)(outp + (size_t)j*128) = pk;
    }
}

// ============================================================
// K4: mma.sync f16 GEMM, K chunked (4 x 64), 3-stage cp.async ring.
// smem: A[3][16K] at 0, B[3][16K] at 49152; epilogue staging reuses.
// ============================================================
#define AB_BUF 16384
#define B_OFF  49152
#define GEMM_SMEM 98304
#define STG_LD 129

__global__ void __launch_bounds__(256) k_mma_gemm(const float* __restrict__ bias,
                                                  float* __restrict__ out) {
    extern __shared__ char sm[];
    const uint32_t sb = smem_u32(sm);
    const int tid = threadIdx.x, wid = tid >> 5, lane = tid & 31;
    const int m0 = blockIdx.x * 128;
    const int n0 = blockIdx.y * 128;

    auto issue = [&](int kc, int p) {
        #pragma unroll
        for (int it = 0; it < 4; ++it) {
            int u = tid + it*256;
            int row = u >> 3, kb = u & 7;
            uint32_t off = (uint32_t)(row*128 + ((kb ^ (row & 7)) << 4));
            const __half* asrc = g_Wh   + (size_t)(m0 + row)*CC + kc*64 + kb*8;
            const __half* bsrc = g_regh + (size_t)(n0 + row)*CC + kc*64 + kb*8;
            uint32_t da = sb + p*AB_BUF + off;
            uint32_t db = sb + B_OFF + p*AB_BUF + off;
            asm volatile("cp.async.cg.shared.global [%0], [%1], 16;" :: "r"(da), "l"(asrc));
            asm volatile("cp.async.cg.shared.global [%0], [%1], 16;" :: "r"(db), "l"(bsrc));
        }
        asm volatile("cp.async.commit_group;");
    };

    const int wm = wid >> 2;
    const int wn = wid & 3;
    const int a_l15 = lane & 15;
    const int a_khi = lane >> 4;
    const int b_l7  = lane & 7;
    const int b_khi = (lane >> 3) & 1;

    uint32_t a_row[4], a_xr[4], b_row[4], b_xr[4];
    #pragma unroll
    for (int mf = 0; mf < 4; ++mf) {
        int mrow = wm*64 + mf*16 + a_l15;
        a_row[mf] = (uint32_t)(mrow*128);
        a_xr[mf] = (uint32_t)(mrow & 7);
    }
    #pragma unroll
    for (int nf = 0; nf < 4; ++nf) {
        int nrow = wn*32 + nf*8 + b_l7;
        b_row[nf] = (uint32_t)(nrow*128);
        b_xr[nf] = (uint32_t)(nrow & 7);
    }

    float acc[4][4][4];
    #pragma unroll
    for (int mf = 0; mf < 4; ++mf)
        #pragma unroll
        for (int nf = 0; nf < 4; ++nf)
            #pragma unroll
            for (int e = 0; e < 4; ++e) acc[mf][nf][e] = 0.f;

    issue(0, 0);
    issue(1, 1);

    #pragma unroll
    for (int kc = 0; kc < 4; ++kc) {
        const int p = kc - (kc >= 3 ? 3 : 0);   // kc % 3 for kc<=3
        if (kc < 3)
            asm volatile("cp.async.wait_group 1;" ::: "memory");
        else
            asm volatile("cp.async.wait_group 0;" ::: "memory");
        __syncthreads();

        if (kc + 2 < 4) issue(kc + 2, (kc + 2) % 3);

        #pragma unroll
        for (int ks = 0; ks < 4; ++ks) {
            uint32_t a[4][4], b[4][2];
            #pragma unroll
            for (int mf = 0; mf < 4; ++mf) {
                uint32_t kb = (uint32_t)(ks*2 + a_khi) ^ a_xr[mf];
                uint32_t addr = sb + p*AB_BUF + a_row[mf] + (kb << 4);
                asm volatile("ldmatrix.sync.aligned.m8n8.x4.shared.b16 {%0,%1,%2,%3}, [%4];"
                             : "=r"(a[mf][0]), "=r"(a[mf][1]), "=r"(a[mf][2]), "=r"(a[mf][3])
                             : "r"(addr));
            }
            #pragma unroll
            for (int nf = 0; nf < 4; ++nf) {
                uint32_t kb = (uint32_t)(ks*2 + b_khi) ^ b_xr[nf];
                uint32_t addr = sb + B_OFF + p*AB_BUF + b_row[nf] + (kb << 4);
                asm volatile("ldmatrix.sync.aligned.m8n8.x2.shared.b16 {%0,%1}, [%2];"
                             : "=r"(b[nf][0]), "=r"(b[nf][1])
                             : "r"(addr));
            }
            #pragma unroll
            for (int mf = 0; mf < 4; ++mf)
                #pragma unroll
                for (int nf = 0; nf < 4; ++nf) {
                    asm volatile(
                        "mma.sync.aligned.m16n8k16.row.col.f32.f16.f16.f32 "
                        "{%0,%1,%2,%3}, {%4,%5,%6,%7}, {%8,%9}, {%0,%1,%2,%3};"
                        : "+f"(acc[mf][nf][0]), "+f"(acc[mf][nf][1]),
                          "+f"(acc[mf][nf][2]), "+f"(acc[mf][nf][3])
                        : "r"(a[mf][0]), "r"(a[mf][1]), "r"(a[mf][2]), "r"(a[mf][3]),
                          "r"(b[nf][0]), "r"(b[nf][1]));
                }
        }
    }
    __syncthreads();   // all MMA reads done before staging overwrites buffers

    float* stgf = (float*)sm;
    const int crow = lane >> 2;
    const int ccol = (lane & 3) * 2;
    #pragma unroll
    for (int mf = 0; mf < 4; ++mf) {
        int mr = wm*64 + mf*16 + crow;
        #pragma unroll
        for (int nf = 0; nf < 4; ++nf) {
            int nc = wn*32 + nf*8 + ccol;
            stgf[mr*STG_LD + nc]         = acc[mf][nf][0];
            stgf[mr*STG_LD + nc + 1]     = acc[mf][nf][1];
            stgf[(mr+8)*STG_LD + nc]     = acc[mf][nf][2];
            stgf[(mr+8)*STG_LD + nc + 1] = acc[mf][nf][3];
        }
    }
    __syncthreads();

    #pragma unroll 4
    for (int i = tid; i < 128*128; i += 256) {
        int m = i >> 7, n = i & 127;
        int nn = n0 + n, o = m0 + m;
        int box = nn / NREG, r = nn - box*NREG;
        out[(size_t)box*(CC*NREG) + (size_t)o*NREG + r] = stgf[m*STG_LD + n] + bias[o];
    }
}

// ============================================================
extern "C" void kernel_launch(void* const* d_in, const int* in_sizes, int n_in,
                              void* d_out, int out_size) {
    const float* fm     = (const float*)d_in[0];
    const float* bboxes = (const float*)d_in[1];
    const float* Wm     = (const float*)d_in[2];
    const float* bias   = (const float*)d_in[3];
    float* out = (float*)d_out;

    cudaFuncSetAttribute(k_mma_gemm, cudaFuncAttributeMaxDynamicSharedMemorySize,
                         GEMM_SMEM);

    k_convw<<<CC, 256>>>(Wm);

    dim3 g1(CC/SLAB, NSTRIP, BB);          // 32 x 20 x 8 = 5120 CTAs
    k_integral<<<g1, 256>>>(fm);

    dim3 gp(HP, BB);
    k_strippfx<<<gp, 256>>>();

    dim3 g3(NBOX, SS);                     // 1024 x 7
    k_gather<<<g3, 64>>>(bboxes, out + RF_ELEMS);

    dim3 g4(2, NTOT/128);
    k_mma_gemm<<<g4, 256, GEMM_SMEM>>>(bias, out);
}